// round 1
// baseline (speedup 1.0000x reference)
#include <cuda_runtime.h>
#include <math.h>
#include <stdint.h>

// Problem shapes (fixed by the dataset)
#define B_ROWS 16384
#define D_DIM  2048
#define D_HALF 1024
#define S_PROTO 64

// ---------------------------------------------------------------------------
// Scratch (device globals; allocation-free per harness rules)
// ---------------------------------------------------------------------------
__device__ float g_h[(size_t)B_ROWS * D_DIM];     // h, later normalized in place
__device__ float g_r[(size_t)B_ROWS * D_HALF];    // gelu(x@Wr1^T + br1)
__device__ float g_tw[(size_t)B_ROWS * 4];        // type softmax weights
__device__ float g_sim[(size_t)B_ROWS * S_PROTO]; // raw_sim
__device__ float g_attn[(size_t)B_ROWS * S_PROTO];
__device__ float g_retr[(size_t)B_ROWS * D_DIM];
__device__ float g_pn[(size_t)S_PROTO * D_DIM];   // normalized prototypes
__device__ float g_base[S_PROTO];                 // additive salience terms
__device__ float g_wsimc[S_PROTO];                // 0.45 * conf[s]

// ---------------------------------------------------------------------------
// Helpers
// ---------------------------------------------------------------------------
__device__ __forceinline__ float gelu_exact(float v) {
    return 0.5f * v * (1.0f + erff(v * 0.70710678118654752440f));
}

__device__ __forceinline__ float block_reduce_sum(float v) {
    __shared__ float sh[32];
    int lane = threadIdx.x & 31, w = threadIdx.x >> 5;
    #pragma unroll
    for (int o = 16; o; o >>= 1) v += __shfl_xor_sync(0xFFFFFFFFu, v, o);
    if (lane == 0) sh[w] = v;
    __syncthreads();
    float r = (threadIdx.x < (blockDim.x >> 5)) ? sh[threadIdx.x] : 0.0f;
    if (w == 0) {
        #pragma unroll
        for (int o = 16; o; o >>= 1) r += __shfl_xor_sync(0xFFFFFFFFu, r, o);
        if (lane == 0) sh[0] = r;
    }
    __syncthreads();
    float out = sh[0];
    __syncthreads();  // safe for back-to-back calls
    return out;
}

// ---------------------------------------------------------------------------
// Generic NT GEMM: C[M,N] = act(A[M,K] * B[N,K]^T + bias) (+ residual)
// MODE bits: 1 = exact GELU, 2 = add Xres row (stride N), 4 = split A
//            (first Ksplit cols from A, rest from A2, both stride Ksplit)
// Double buffered, 8x8 per-thread tile, fp32.
// ---------------------------------------------------------------------------
template<int BM, int BN, int BK, int TM, int TN, int MODE>
__global__ void __launch_bounds__((BM/TM)*(BN/TN))
gemm_nt(const float* __restrict__ A, const float* __restrict__ A2, int Ksplit,
        const float* __restrict__ Bm, const float* __restrict__ bias,
        const float* __restrict__ Xres, float* __restrict__ C,
        int M, int N, int K)
{
    constexpr int THREADS = (BM/TM)*(BN/TN);
    constexpr int PAD = 4;
    constexpr int KV  = BK / 4;                  // float4 per K-row
    constexpr int ALD = (BM*BK) / (4*THREADS);   // A float4 loads per thread
    constexpr int BLD = (BN*BK) / (4*THREADS);

    __shared__ float As[2][BK][BM + PAD];
    __shared__ float Bs[2][BK][BN + PAD];

    const int tid = threadIdx.x;
    const int m0 = blockIdx.y * BM;
    const int n0 = blockIdx.x * BN;
    const int tcols = BN / TN;
    const int tr = tid / tcols;
    const int tc = tid % tcols;

    float4 aReg[ALD], bReg[BLD];

    float acc[TM][TN];
    #pragma unroll
    for (int i = 0; i < TM; i++)
        #pragma unroll
        for (int j = 0; j < TN; j++) acc[i][j] = 0.0f;

    // --- fetch global -> regs ---
    auto fetch = [&](int kt) {
        #pragma unroll
        for (int i = 0; i < ALD; i++) {
            int idx = tid + i * THREADS;
            int row = idx / KV;
            int kc  = (idx % KV) * 4;
            int gk  = kt + kc;
            const float* src;
            if constexpr (MODE & 4) {
                src = (gk < Ksplit)
                    ? (A  + (size_t)(m0 + row) * Ksplit + gk)
                    : (A2 + (size_t)(m0 + row) * Ksplit + (gk - Ksplit));
            } else {
                src = A + (size_t)(m0 + row) * K + gk;
            }
            aReg[i] = *reinterpret_cast<const float4*>(src);
        }
        #pragma unroll
        for (int i = 0; i < BLD; i++) {
            int idx = tid + i * THREADS;
            int row = idx / KV;
            int kc  = (idx % KV) * 4;
            bReg[i] = *reinterpret_cast<const float4*>(
                Bm + (size_t)(n0 + row) * K + kt + kc);
        }
    };
    // --- store regs -> smem (transposed to [k][m]) ---
    auto stash = [&](int buf) {
        #pragma unroll
        for (int i = 0; i < ALD; i++) {
            int idx = tid + i * THREADS;
            int row = idx / KV;
            int kc  = (idx % KV) * 4;
            As[buf][kc+0][row] = aReg[i].x; As[buf][kc+1][row] = aReg[i].y;
            As[buf][kc+2][row] = aReg[i].z; As[buf][kc+3][row] = aReg[i].w;
        }
        #pragma unroll
        for (int i = 0; i < BLD; i++) {
            int idx = tid + i * THREADS;
            int row = idx / KV;
            int kc  = (idx % KV) * 4;
            Bs[buf][kc+0][row] = bReg[i].x; Bs[buf][kc+1][row] = bReg[i].y;
            Bs[buf][kc+2][row] = bReg[i].z; Bs[buf][kc+3][row] = bReg[i].w;
        }
    };

    fetch(0); stash(0);
    __syncthreads();

    const int nk = K / BK;
    for (int t = 0; t < nk; t++) {
        const int cur = t & 1;
        if (t + 1 < nk) fetch((t + 1) * BK);   // LDGs issued early

        #pragma unroll
        for (int k = 0; k < BK; k++) {
            float a[TM], b[TN];
            #pragma unroll
            for (int i = 0; i < TM; i += 4) {
                float4 v = *reinterpret_cast<const float4*>(&As[cur][k][tr*TM + i]);
                a[i] = v.x; a[i+1] = v.y; a[i+2] = v.z; a[i+3] = v.w;
            }
            #pragma unroll
            for (int j = 0; j < TN; j += 4) {
                float4 v = *reinterpret_cast<const float4*>(&Bs[cur][k][tc*TN + j]);
                b[j] = v.x; b[j+1] = v.y; b[j+2] = v.z; b[j+3] = v.w;
            }
            #pragma unroll
            for (int i = 0; i < TM; i++)
                #pragma unroll
                for (int j = 0; j < TN; j++)
                    acc[i][j] = fmaf(a[i], b[j], acc[i][j]);
        }
        if (t + 1 < nk) stash(cur ^ 1);
        __syncthreads();
    }

    // --- epilogue ---
    #pragma unroll
    for (int i = 0; i < TM; i++) {
        const int row = m0 + tr * TM + i;
        #pragma unroll
        for (int j = 0; j < TN; j += 4) {
            const int col = n0 + tc * TN + j;
            float4 v;
            v.x = acc[i][j];   v.y = acc[i][j+1];
            v.z = acc[i][j+2]; v.w = acc[i][j+3];
            if (bias) {
                v.x += bias[col];   v.y += bias[col+1];
                v.z += bias[col+2]; v.w += bias[col+3];
            }
            if constexpr (MODE & 1) {
                v.x = gelu_exact(v.x); v.y = gelu_exact(v.y);
                v.z = gelu_exact(v.z); v.w = gelu_exact(v.w);
            }
            if constexpr (MODE & 2) {
                float4 xr = *reinterpret_cast<const float4*>(
                    &Xres[(size_t)row * N + col]);
                v.x += xr.x; v.y += xr.y; v.z += xr.z; v.w += xr.w;
            }
            *reinterpret_cast<float4*>(&C[(size_t)row * N + col]) = v;
        }
    }
}

// ---------------------------------------------------------------------------
// Prototype prep: normalize prototypes + per-proto static salience terms
// grid = S_PROTO blocks, 256 threads
// ---------------------------------------------------------------------------
__global__ void proto_prep(const float* __restrict__ protos,
                           const float* __restrict__ conf,
                           const float* __restrict__ age,
                           const float* __restrict__ ev)
{
    const int s = blockIdx.x;
    float ss = 0.0f;
    for (int k = threadIdx.x; k < D_DIM; k += 256) {
        float v = protos[(size_t)s * D_DIM + k];
        ss += v * v;
    }
    float tot = block_reduce_sum(ss);
    float scale = 1.0f / fmaxf(sqrtf(tot), 1e-12f);
    for (int k = threadIdx.x; k < D_DIM; k += 256)
        g_pn[(size_t)s * D_DIM + k] = protos[(size_t)s * D_DIM + k] * scale;

    if (threadIdx.x == 0) {
        float evmax = 0.0f;
        for (int i = 0; i < S_PROTO; i++) evmax = fmaxf(evmax, ev[i]);
        float freq = logf(ev[s] + 1.0f) / (logf(evmax + 2.0f) + 1e-8f);
        float rec  = expf(-age[s] * (1.0f / 200.0f));
        g_base[s]  = 0.2f * rec + 0.15f * freq + 0.1f * conf[s] + 0.1f * 0.9f;
        g_wsimc[s] = 0.45f * conf[s];
    }
}

// ---------------------------------------------------------------------------
// Row L2-normalize h in place. grid = B_ROWS, 256 threads (8 f32 per thread)
// ---------------------------------------------------------------------------
__global__ void rownorm_inplace(float* __restrict__ h)
{
    const size_t base = (size_t)blockIdx.x * D_DIM;
    float4* hp = reinterpret_cast<float4*>(h + base);
    float4 v[2];
    float ss = 0.0f;
    #pragma unroll
    for (int i = 0; i < 2; i++) {
        v[i] = hp[threadIdx.x + 256 * i];
        ss += v[i].x*v[i].x + v[i].y*v[i].y + v[i].z*v[i].z + v[i].w*v[i].w;
    }
    float tot = block_reduce_sum(ss);
    float scale = 1.0f / fmaxf(sqrtf(tot), 1e-12f);
    #pragma unroll
    for (int i = 0; i < 2; i++) {
        v[i].x *= scale; v[i].y *= scale; v[i].z *= scale; v[i].w *= scale;
        hp[threadIdx.x + 256 * i] = v[i];
    }
}

// ---------------------------------------------------------------------------
// Type weights: tw[b] = softmax(r[b] @ Wr2^T + br2). 1 warp per row.
// grid = B/8, 256 threads
// ---------------------------------------------------------------------------
__global__ void type_weights_kernel(const float* __restrict__ r,
                                    const float* __restrict__ Wr2,
                                    const float* __restrict__ br2,
                                    float* __restrict__ tw)
{
    const int warp = threadIdx.x >> 5, lane = threadIdx.x & 31;
    const int b = blockIdx.x * 8 + warp;
    const float4* rp = reinterpret_cast<const float4*>(r + (size_t)b * D_HALF);
    float acc[4] = {0.f, 0.f, 0.f, 0.f};
    for (int i = lane; i < D_HALF / 4; i += 32) {
        float4 rv = rp[i];
        #pragma unroll
        for (int t = 0; t < 4; t++) {
            float4 wv = reinterpret_cast<const float4*>(Wr2 + (size_t)t * D_HALF)[i];
            acc[t] += rv.x*wv.x + rv.y*wv.y + rv.z*wv.z + rv.w*wv.w;
        }
    }
    #pragma unroll
    for (int t = 0; t < 4; t++)
        #pragma unroll
        for (int o = 16; o; o >>= 1)
            acc[t] += __shfl_xor_sync(0xFFFFFFFFu, acc[t], o);
    if (lane == 0) {
        float z[4], m = -1e30f;
        #pragma unroll
        for (int t = 0; t < 4; t++) { z[t] = acc[t] + br2[t]; m = fmaxf(m, z[t]); }
        float s = 0.0f;
        #pragma unroll
        for (int t = 0; t < 4; t++) { z[t] = expf(z[t] - m); s += z[t]; }
        float inv = 1.0f / s;
        #pragma unroll
        for (int t = 0; t < 4; t++) tw[(size_t)b * 4 + t] = z[t] * inv;
    }
}

// ---------------------------------------------------------------------------
// Salience + softmax over S=64. 1 warp per row (2 protos/lane).
// grid = B/8, 256 threads
// ---------------------------------------------------------------------------
__global__ void sal_softmax_kernel(const float* __restrict__ sim,
                                   const float* __restrict__ tw,
                                   float* __restrict__ attn)
{
    const int warp = threadIdx.x >> 5, lane = threadIdx.x & 31;
    const int b = blockIdx.x * 8 + warp;
    float sal[2];
    #pragma unroll
    for (int i = 0; i < 2; i++) {
        int s = lane + 32 * i;
        float v = g_wsimc[s] * tw[(size_t)b * 4 + (s >> 4)]
                * sim[(size_t)b * S_PROTO + s] + g_base[s];
        sal[i] = fminf(fmaxf(v, 0.0f), 1.0f);
    }
    float m = fmaxf(sal[0], sal[1]);
    #pragma unroll
    for (int o = 16; o; o >>= 1) m = fmaxf(m, __shfl_xor_sync(0xFFFFFFFFu, m, o));
    const float invT = 1.0f / 0.07f;
    float e0 = expf((sal[0] - m) * invT);
    float e1 = expf((sal[1] - m) * invT);
    float s = e0 + e1;
    #pragma unroll
    for (int o = 16; o; o >>= 1) s += __shfl_xor_sync(0xFFFFFFFFu, s, o);
    float inv = 1.0f / s;
    attn[(size_t)b * S_PROTO + lane]      = e0 * inv;
    attn[(size_t)b * S_PROTO + lane + 32] = e1 * inv;
}

// ---------------------------------------------------------------------------
// retrieved = attn @ prototypes.  16 rows x 256 cols per block.
// grid = (D/256, B/16), 256 threads
// ---------------------------------------------------------------------------
__global__ void retrieve_kernel(const float* __restrict__ attn,
                                const float* __restrict__ protos,
                                float* __restrict__ out)
{
    __shared__ float sA[16][S_PROTO];
    const int tid = threadIdx.x;
    const int r0 = blockIdx.y * 16;
    for (int i = tid; i < 16 * S_PROTO; i += 256)
        sA[i / S_PROTO][i % S_PROTO] =
            attn[(size_t)(r0 + i / S_PROTO) * S_PROTO + (i % S_PROTO)];
    __syncthreads();

    const int n = blockIdx.x * 256 + tid;
    float acc[16];
    #pragma unroll
    for (int r = 0; r < 16; r++) acc[r] = 0.0f;
    for (int s = 0; s < S_PROTO; s++) {
        float p = protos[(size_t)s * D_DIM + n];
        #pragma unroll
        for (int r = 0; r < 16; r++) acc[r] = fmaf(sA[r][s], p, acc[r]);
    }
    #pragma unroll
    for (int r = 0; r < 16; r++)
        out[(size_t)(r0 + r) * D_DIM + n] = acc[r];
}

// ---------------------------------------------------------------------------
// In-place LayerNorm over D. grid = B_ROWS, 256 threads.
// ---------------------------------------------------------------------------
__global__ void layernorm_inplace(float* __restrict__ y,
                                  const float* __restrict__ w,
                                  const float* __restrict__ bb)
{
    const size_t base = (size_t)blockIdx.x * D_DIM;
    float4* yp = reinterpret_cast<float4*>(y + base);
    float4 v[2];
    float sum = 0.0f;
    #pragma unroll
    for (int i = 0; i < 2; i++) {
        v[i] = yp[threadIdx.x + 256 * i];
        sum += v[i].x + v[i].y + v[i].z + v[i].w;
    }
    float mu = block_reduce_sum(sum) * (1.0f / D_DIM);
    float sq = 0.0f;
    #pragma unroll
    for (int i = 0; i < 2; i++) {
        float dx = v[i].x - mu, dy = v[i].y - mu, dz = v[i].z - mu, dw = v[i].w - mu;
        sq += dx*dx + dy*dy + dz*dz + dw*dw;
    }
    float var = block_reduce_sum(sq) * (1.0f / D_DIM);
    float rstd = rsqrtf(var + 1e-5f);
    #pragma unroll
    for (int i = 0; i < 2; i++) {
        int col = (threadIdx.x + 256 * i) * 4;
        float4 wv = *reinterpret_cast<const float4*>(&w[col]);
        float4 bv = *reinterpret_cast<const float4*>(&bb[col]);
        float4 o;
        o.x = wv.x * (v[i].x - mu) * rstd + bv.x;
        o.y = wv.y * (v[i].y - mu) * rstd + bv.y;
        o.z = wv.z * (v[i].z - mu) * rstd + bv.z;
        o.w = wv.w * (v[i].w - mu) * rstd + bv.w;
        yp[threadIdx.x + 256 * i] = o;
    }
}

// ---------------------------------------------------------------------------
// Launch
// ---------------------------------------------------------------------------
extern "C" void kernel_launch(void* const* d_in, const int* in_sizes, int n_in,
                              void* d_out, int out_size)
{
    const float* x      = (const float*)d_in[0];
    const float* protos = (const float*)d_in[1];
    const float* conf   = (const float*)d_in[2];
    const float* age    = (const float*)d_in[3];
    const float* ev     = (const float*)d_in[4];
    const float* W_in   = (const float*)d_in[5];
    const float* b_in   = (const float*)d_in[6];
    const float* Wr1    = (const float*)d_in[7];
    const float* br1    = (const float*)d_in[8];
    const float* Wr2    = (const float*)d_in[9];
    const float* br2    = (const float*)d_in[10];
    const float* W_out  = (const float*)d_in[11];
    const float* b_out  = (const float*)d_in[12];
    const float* ln_w   = (const float*)d_in[13];
    const float* ln_b   = (const float*)d_in[14];
    float* out = (float*)d_out;

    float *h, *r, *tw, *sim, *attn, *retr, *pn;
    cudaGetSymbolAddress((void**)&h,    g_h);
    cudaGetSymbolAddress((void**)&r,    g_r);
    cudaGetSymbolAddress((void**)&tw,   g_tw);
    cudaGetSymbolAddress((void**)&sim,  g_sim);
    cudaGetSymbolAddress((void**)&attn, g_attn);
    cudaGetSymbolAddress((void**)&retr, g_retr);
    cudaGetSymbolAddress((void**)&pn,   g_pn);

    const int B = B_ROWS;

    // h = x @ W_in^T + b_in
    gemm_nt<128,128,16,8,8,0><<<dim3(D_DIM/128, B/128), 256>>>(
        x, nullptr, 0, W_in, b_in, nullptr, h, B, D_DIM, D_DIM);

    // r = gelu(x @ Wr1^T + br1)
    gemm_nt<128,128,16,8,8,1><<<dim3(D_HALF/128, B/128), 256>>>(
        x, nullptr, 0, Wr1, br1, nullptr, r, B, D_HALF, D_DIM);

    // type softmax
    type_weights_kernel<<<B/8, 256>>>(r, Wr2, br2, tw);

    // prototype normalization + static salience terms
    proto_prep<<<S_PROTO, 256>>>(protos, conf, age, ev);

    // normalize h rows in place
    rownorm_inplace<<<B, 256>>>(h);

    // sim = h_norm @ p_norm^T   (N = 64)
    gemm_nt<128,64,16,8,4,0><<<dim3(1, B/128), 256>>>(
        h, nullptr, 0, pn, nullptr, nullptr, sim, B, S_PROTO, D_DIM);

    // salience + softmax over prototypes
    sal_softmax_kernel<<<B/8, 256>>>(sim, tw, attn);

    // retrieved = attn @ prototypes
    retrieve_kernel<<<dim3(D_DIM/256, B/16), 256>>>(attn, protos, retr);

    // y = gelu([x, retrieved] @ W_out^T + b_out) + x   -> d_out
    gemm_nt<128,128,16,8,8,(1|2|4)><<<dim3(D_DIM/128, B/128), 256>>>(
        x, retr, D_DIM, W_out, b_out, x, out, B, D_DIM, 2 * D_DIM);

    // final LayerNorm in place on d_out
    layernorm_inplace<<<B, 256>>>(out, ln_w, ln_b);
}

// round 3
// speedup vs baseline: 2.5231x; 2.5231x over previous
#include <cuda_runtime.h>
#include <cuda_bf16.h>
#include <math.h>
#include <stdint.h>

#define B_ROWS 16384
#define D_DIM  2048
#define D_HALF 1024
#define S_PROTO 64

// ---------------------------------------------------------------------------
// Scratch (device globals; allocation-free per harness rules)
// ---------------------------------------------------------------------------
__device__ __nv_bfloat16 g_x_hi[(size_t)B_ROWS * D_DIM];
__device__ __nv_bfloat16 g_x_lo[(size_t)B_ROWS * D_DIM];
__device__ __nv_bfloat16 g_Win_hi[(size_t)D_DIM * D_DIM];
__device__ __nv_bfloat16 g_Win_lo[(size_t)D_DIM * D_DIM];
__device__ __nv_bfloat16 g_Wr1_hi[(size_t)D_HALF * D_DIM];
__device__ __nv_bfloat16 g_Wr1_lo[(size_t)D_HALF * D_DIM];
__device__ __nv_bfloat16 g_Wout_hi[(size_t)D_DIM * 2 * D_DIM];
__device__ __nv_bfloat16 g_Wout_lo[(size_t)D_DIM * 2 * D_DIM];
__device__ __nv_bfloat16 g_retr_hi[(size_t)B_ROWS * D_DIM];
__device__ __nv_bfloat16 g_retr_lo[(size_t)B_ROWS * D_DIM];
__device__ float g_h[(size_t)B_ROWS * D_DIM];
__device__ float g_r[(size_t)B_ROWS * D_HALF];
__device__ float g_tw[(size_t)B_ROWS * 4];
__device__ float g_sim[(size_t)B_ROWS * S_PROTO];
__device__ float g_attn[(size_t)B_ROWS * S_PROTO];
__device__ float g_pn[(size_t)S_PROTO * D_DIM];
__device__ float g_base[S_PROTO];
__device__ float g_wsimc[S_PROTO];

// ---------------------------------------------------------------------------
// PTX helpers (baseline ISA only: mma.sync / ldmatrix / cp.async)
// ---------------------------------------------------------------------------
__device__ __forceinline__ uint32_t smem_to_u32(const void* p) {
    uint32_t a;
    asm("{ .reg .u64 t; cvta.to.shared.u64 t, %1; cvt.u32.u64 %0, t; }"
        : "=r"(a) : "l"(p));
    return a;
}

__device__ __forceinline__ void cpasync16(uint32_t saddr, const void* g) {
    asm volatile("cp.async.cg.shared.global [%0], [%1], 16;"
                 :: "r"(saddr), "l"(g));
}
#define CP_COMMIT() asm volatile("cp.async.commit_group;" ::: "memory")
#define CP_WAIT(n)  asm volatile("cp.async.wait_group %0;" :: "n"(n) : "memory")

__device__ __forceinline__ void ldsm4(uint32_t* r, uint32_t addr) {
    asm volatile("ldmatrix.sync.aligned.m8n8.x4.shared.b16 {%0,%1,%2,%3}, [%4];"
                 : "=r"(r[0]), "=r"(r[1]), "=r"(r[2]), "=r"(r[3]) : "r"(addr));
}

__device__ __forceinline__ void mma_bf16(float* d, const uint32_t* a, const uint32_t* b) {
    asm volatile(
        "mma.sync.aligned.m16n8k16.row.col.f32.bf16.bf16.f32 "
        "{%0,%1,%2,%3}, {%4,%5,%6,%7}, {%8,%9}, {%0,%1,%2,%3};"
        : "+f"(d[0]), "+f"(d[1]), "+f"(d[2]), "+f"(d[3])
        : "r"(a[0]), "r"(a[1]), "r"(a[2]), "r"(a[3]), "r"(b[0]), "r"(b[1]));
}

// ---------------------------------------------------------------------------
// Misc helpers
// ---------------------------------------------------------------------------
__device__ __forceinline__ float gelu_exact(float v) {
    return 0.5f * v * (1.0f + erff(v * 0.70710678118654752440f));
}

__device__ __forceinline__ float block_reduce_sum(float v) {
    __shared__ float sh[32];
    int lane = threadIdx.x & 31, w = threadIdx.x >> 5;
    #pragma unroll
    for (int o = 16; o; o >>= 1) v += __shfl_xor_sync(0xFFFFFFFFu, v, o);
    if (lane == 0) sh[w] = v;
    __syncthreads();
    float r = (threadIdx.x < (blockDim.x >> 5)) ? sh[threadIdx.x] : 0.0f;
    if (w == 0) {
        #pragma unroll
        for (int o = 16; o; o >>= 1) r += __shfl_xor_sync(0xFFFFFFFFu, r, o);
        if (lane == 0) sh[0] = r;
    }
    __syncthreads();
    float out = sh[0];
    __syncthreads();
    return out;
}

// ---------------------------------------------------------------------------
// fp32 -> (bf16 hi, bf16 lo) split
// ---------------------------------------------------------------------------
__device__ __forceinline__ void split2(float a, float b, uint32_t& hi, uint32_t& lo) {
    __nv_bfloat162 h = __floats2bfloat162_rn(a, b);
    float2 hf = __bfloat1622float2(h);
    __nv_bfloat162 l = __floats2bfloat162_rn(a - hf.x, b - hf.y);
    hi = *reinterpret_cast<uint32_t*>(&h);
    lo = *reinterpret_cast<uint32_t*>(&l);
}

__global__ void split_kernel(const float* __restrict__ s,
                             __nv_bfloat16* __restrict__ hi,
                             __nv_bfloat16* __restrict__ lo, size_t n4)
{
    size_t i = (size_t)blockIdx.x * blockDim.x + threadIdx.x;
    if (i >= n4) return;
    float4 v = reinterpret_cast<const float4*>(s)[i];
    uint2 ph, pl;
    split2(v.x, v.y, ph.x, pl.x);
    split2(v.z, v.w, ph.y, pl.y);
    reinterpret_cast<uint2*>(hi)[i] = ph;
    reinterpret_cast<uint2*>(lo)[i] = pl;
}

// ---------------------------------------------------------------------------
// HMMA (mma.sync bf16, 3-pass split) GEMM:
//   C[M,N] = act(A*B^T + bias) (+ residual)
// MODE: 1=gelu, 2=+Xres, 4=split-A (k<Ksplit from A, else A2; both stride strideA)
// BM=BN=128, BK=32, 3-stage cp.async pipeline, 256 threads,
// 8 warps in 2x4, warp tile 64x32.
// ---------------------------------------------------------------------------
template<int MODE>
__global__ void __launch_bounds__(256, 1)
mma_gemm(const __nv_bfloat16* __restrict__ Ahi, const __nv_bfloat16* __restrict__ Alo,
         const __nv_bfloat16* __restrict__ A2hi, const __nv_bfloat16* __restrict__ A2lo,
         const __nv_bfloat16* __restrict__ Bhi, const __nv_bfloat16* __restrict__ Blo,
         const float* __restrict__ bias, const float* __restrict__ Xres,
         float* __restrict__ C, int M, int N, int K, int Ksplit, int strideA)
{
    constexpr int BM = 128, BN = 128, BK = 32, STAGES = 3;
    constexpr int TILE_B  = BM * BK * 2;      // 8192 bytes per matrix tile
    constexpr int STAGE_B = 4 * TILE_B;       // Ahi, Alo, Bhi, Blo

    extern __shared__ __align__(16) char smem[];
    const uint32_t sbase = smem_to_u32(smem);

    const int tid  = threadIdx.x;
    const int wid  = tid >> 5, lane = tid & 31;
    const int m0 = blockIdx.y * BM;
    const int n0 = blockIdx.x * BN;
    const int wm = (wid >> 2) * 64;   // warp row origin in tile
    const int wn = (wid & 3) * 32;    // warp col origin in tile

    float acc[4][4][4];
    #pragma unroll
    for (int i = 0; i < 4; i++)
        #pragma unroll
        for (int j = 0; j < 4; j++)
            #pragma unroll
            for (int k = 0; k < 4; k++) acc[i][j][k] = 0.0f;

    const int nk = K / BK;

    auto load_stage = [&](int s, int t) {
        const int k0 = t * BK;
        const __nv_bfloat16 *pAh = Ahi, *pAl = Alo;
        int ka = k0;
        if constexpr (MODE & 4) {
            if (k0 >= Ksplit) { pAh = A2hi; pAl = A2lo; ka = k0 - Ksplit; }
        }
        const uint32_t sb = sbase + s * STAGE_B;
        #pragma unroll
        for (int i = 0; i < 2; i++) {
            int idx = tid + i * 256;           // 512 chunks per matrix
            int row = idx >> 2, g = idx & 3;   // 4 x 16B groups per 64B row
            int gs  = g ^ (row & 3);           // xor swizzle
            uint32_t so = row * 64 + gs * 16;
            size_t ga = (size_t)(m0 + row) * strideA + ka + g * 8;
            size_t gb = (size_t)(n0 + row) * K + k0 + g * 8;
            cpasync16(sb + 0 * TILE_B + so, pAh + ga);
            cpasync16(sb + 1 * TILE_B + so, pAl + ga);
            cpasync16(sb + 2 * TILE_B + so, Bhi + gb);
            cpasync16(sb + 3 * TILE_B + so, Blo + gb);
        }
    };

    auto compute_stage = [&](int s) {
        const uint32_t sb = sbase + s * STAGE_B;
        #pragma unroll
        for (int ks = 0; ks < 2; ks++) {
            uint32_t ahi[4][4], alo[4][4], bhi[2][4], blo[2][4];
            #pragma unroll
            for (int mf = 0; mf < 4; mf++) {
                int row = wm + mf * 16 + (lane & 15);
                int g   = ks * 2 + (lane >> 4);
                uint32_t addr = sb + row * 64 + ((g ^ (row & 3)) * 16);
                ldsm4(ahi[mf], addr);
                ldsm4(alo[mf], addr + TILE_B);
            }
            #pragma unroll
            for (int nf2 = 0; nf2 < 2; nf2++) {
                int nrow = wn + nf2 * 16 + ((lane >> 4) & 1) * 8 + (lane & 7);
                int g    = ks * 2 + ((lane >> 3) & 1);
                uint32_t addr = sb + 2 * TILE_B + nrow * 64 + ((g ^ (nrow & 3)) * 16);
                ldsm4(bhi[nf2], addr);
                ldsm4(blo[nf2], addr + TILE_B);
            }
            #pragma unroll
            for (int mf = 0; mf < 4; mf++)
                #pragma unroll
                for (int nf = 0; nf < 4; nf++) {
                    const uint32_t* bh = &bhi[nf >> 1][(nf & 1) * 2];
                    const uint32_t* bl = &blo[nf >> 1][(nf & 1) * 2];
                    mma_bf16(acc[mf][nf], ahi[mf], bh);
                    mma_bf16(acc[mf][nf], ahi[mf], bl);
                    mma_bf16(acc[mf][nf], alo[mf], bh);
                }
        }
    };

    // prologue: stages 0..STAGES-2
    load_stage(0, 0); CP_COMMIT();
    load_stage(1, 1); CP_COMMIT();

    for (int t = 0; t < nk; t++) {
        CP_WAIT(STAGES - 2);
        __syncthreads();
        if (t + STAGES - 1 < nk) load_stage((t + STAGES - 1) % STAGES, t + STAGES - 1);
        CP_COMMIT();
        compute_stage(t % STAGES);
    }

    // epilogue: registers -> global with fused bias / gelu / residual
    #pragma unroll
    for (int mf = 0; mf < 4; mf++)
        #pragma unroll
        for (int nf = 0; nf < 4; nf++)
            #pragma unroll
            for (int half = 0; half < 2; half++) {
                int row = m0 + wm + mf * 16 + (lane >> 2) + half * 8;
                int col = n0 + wn + nf * 8 + (lane & 3) * 2;
                float v0 = acc[mf][nf][half * 2 + 0] + bias[col];
                float v1 = acc[mf][nf][half * 2 + 1] + bias[col + 1];
                if constexpr (MODE & 1) { v0 = gelu_exact(v0); v1 = gelu_exact(v1); }
                if constexpr (MODE & 2) {
                    float2 xr = *reinterpret_cast<const float2*>(
                        &Xres[(size_t)row * N + col]);
                    v0 += xr.x; v1 += xr.y;
                }
                float2 o; o.x = v0; o.y = v1;
                *reinterpret_cast<float2*>(&C[(size_t)row * N + col]) = o;
            }
}

// ---------------------------------------------------------------------------
// SIMT NT GEMM (kept for sim = h_norm @ p_norm^T, N=64, fp32)
// ---------------------------------------------------------------------------
template<int BM, int BN, int BK, int TM, int TN>
__global__ void __launch_bounds__((BM/TM)*(BN/TN))
gemm_nt(const float* __restrict__ A, const float* __restrict__ Bm,
        float* __restrict__ C, int M, int N, int K)
{
    constexpr int THREADS = (BM/TM)*(BN/TN);
    constexpr int PAD = 4;
    constexpr int KV  = BK / 4;
    constexpr int ALD = (BM*BK) / (4*THREADS);
    constexpr int BLD = (BN*BK) / (4*THREADS);

    __shared__ float As[2][BK][BM + PAD];
    __shared__ float Bs[2][BK][BN + PAD];

    const int tid = threadIdx.x;
    const int m0 = blockIdx.y * BM;
    const int n0 = blockIdx.x * BN;
    const int tcols = BN / TN;
    const int tr = tid / tcols;
    const int tc = tid % tcols;

    float4 aReg[ALD], bReg[BLD];
    float acc[TM][TN];
    #pragma unroll
    for (int i = 0; i < TM; i++)
        #pragma unroll
        for (int j = 0; j < TN; j++) acc[i][j] = 0.0f;

    auto fetch = [&](int kt) {
        #pragma unroll
        for (int i = 0; i < ALD; i++) {
            int idx = tid + i * THREADS;
            int row = idx / KV, kc = (idx % KV) * 4;
            aReg[i] = *reinterpret_cast<const float4*>(A + (size_t)(m0+row)*K + kt + kc);
        }
        #pragma unroll
        for (int i = 0; i < BLD; i++) {
            int idx = tid + i * THREADS;
            int row = idx / KV, kc = (idx % KV) * 4;
            bReg[i] = *reinterpret_cast<const float4*>(Bm + (size_t)(n0+row)*K + kt + kc);
        }
    };
    auto stash = [&](int buf) {
        #pragma unroll
        for (int i = 0; i < ALD; i++) {
            int idx = tid + i * THREADS;
            int row = idx / KV, kc = (idx % KV) * 4;
            As[buf][kc+0][row] = aReg[i].x; As[buf][kc+1][row] = aReg[i].y;
            As[buf][kc+2][row] = aReg[i].z; As[buf][kc+3][row] = aReg[i].w;
        }
        #pragma unroll
        for (int i = 0; i < BLD; i++) {
            int idx = tid + i * THREADS;
            int row = idx / KV, kc = (idx % KV) * 4;
            Bs[buf][kc+0][row] = bReg[i].x; Bs[buf][kc+1][row] = bReg[i].y;
            Bs[buf][kc+2][row] = bReg[i].z; Bs[buf][kc+3][row] = bReg[i].w;
        }
    };

    fetch(0); stash(0);
    __syncthreads();

    const int nk = K / BK;
    for (int t = 0; t < nk; t++) {
        const int cur = t & 1;
        if (t + 1 < nk) fetch((t + 1) * BK);
        #pragma unroll
        for (int k = 0; k < BK; k++) {
            float a[TM], b[TN];
            #pragma unroll
            for (int i = 0; i < TM; i += 4) {
                float4 v = *reinterpret_cast<const float4*>(&As[cur][k][tr*TM + i]);
                a[i]=v.x; a[i+1]=v.y; a[i+2]=v.z; a[i+3]=v.w;
            }
            #pragma unroll
            for (int j = 0; j < TN; j += 4) {
                float4 v = *reinterpret_cast<const float4*>(&Bs[cur][k][tc*TN + j]);
                b[j]=v.x; b[j+1]=v.y; b[j+2]=v.z; b[j+3]=v.w;
            }
            #pragma unroll
            for (int i = 0; i < TM; i++)
                #pragma unroll
                for (int j = 0; j < TN; j++)
                    acc[i][j] = fmaf(a[i], b[j], acc[i][j]);
        }
        if (t + 1 < nk) stash(cur ^ 1);
        __syncthreads();
    }

    #pragma unroll
    for (int i = 0; i < TM; i++) {
        const int row = m0 + tr * TM + i;
        #pragma unroll
        for (int j = 0; j < TN; j += 4) {
            const int col = n0 + tc * TN + j;
            float4 v;
            v.x = acc[i][j]; v.y = acc[i][j+1]; v.z = acc[i][j+2]; v.w = acc[i][j+3];
            *reinterpret_cast<float4*>(&C[(size_t)row * N + col]) = v;
        }
    }
}

// ---------------------------------------------------------------------------
// Prototype prep
// ---------------------------------------------------------------------------
__global__ void proto_prep(const float* __restrict__ protos,
                           const float* __restrict__ conf,
                           const float* __restrict__ age,
                           const float* __restrict__ ev)
{
    const int s = blockIdx.x;
    float ss = 0.0f;
    for (int k = threadIdx.x; k < D_DIM; k += 256) {
        float v = protos[(size_t)s * D_DIM + k];
        ss += v * v;
    }
    float tot = block_reduce_sum(ss);
    float scale = 1.0f / fmaxf(sqrtf(tot), 1e-12f);
    for (int k = threadIdx.x; k < D_DIM; k += 256)
        g_pn[(size_t)s * D_DIM + k] = protos[(size_t)s * D_DIM + k] * scale;

    if (threadIdx.x == 0) {
        float evmax = 0.0f;
        for (int i = 0; i < S_PROTO; i++) evmax = fmaxf(evmax, ev[i]);
        float freq = logf(ev[s] + 1.0f) / (logf(evmax + 2.0f) + 1e-8f);
        float rec  = expf(-age[s] * (1.0f / 200.0f));
        g_base[s]  = 0.2f * rec + 0.15f * freq + 0.1f * conf[s] + 0.1f * 0.9f;
        g_wsimc[s] = 0.45f * conf[s];
    }
}

// ---------------------------------------------------------------------------
// Row L2-normalize h in place
// ---------------------------------------------------------------------------
__global__ void rownorm_inplace(float* __restrict__ h)
{
    const size_t base = (size_t)blockIdx.x * D_DIM;
    float4* hp = reinterpret_cast<float4*>(h + base);
    float4 v[2];
    float ss = 0.0f;
    #pragma unroll
    for (int i = 0; i < 2; i++) {
        v[i] = hp[threadIdx.x + 256 * i];
        ss += v[i].x*v[i].x + v[i].y*v[i].y + v[i].z*v[i].z + v[i].w*v[i].w;
    }
    float tot = block_reduce_sum(ss);
    float scale = 1.0f / fmaxf(sqrtf(tot), 1e-12f);
    #pragma unroll
    for (int i = 0; i < 2; i++) {
        v[i].x *= scale; v[i].y *= scale; v[i].z *= scale; v[i].w *= scale;
        hp[threadIdx.x + 256 * i] = v[i];
    }
}

// ---------------------------------------------------------------------------
// Type weights softmax (4 logits). 1 warp per row.
// ---------------------------------------------------------------------------
__global__ void type_weights_kernel(const float* __restrict__ r,
                                    const float* __restrict__ Wr2,
                                    const float* __restrict__ br2,
                                    float* __restrict__ tw)
{
    const int warp = threadIdx.x >> 5, lane = threadIdx.x & 31;
    const int b = blockIdx.x * 8 + warp;
    const float4* rp = reinterpret_cast<const float4*>(r + (size_t)b * D_HALF);
    float acc[4] = {0.f, 0.f, 0.f, 0.f};
    for (int i = lane; i < D_HALF / 4; i += 32) {
        float4 rv = rp[i];
        #pragma unroll
        for (int t = 0; t < 4; t++) {
            float4 wv = reinterpret_cast<const float4*>(Wr2 + (size_t)t * D_HALF)[i];
            acc[t] += rv.x*wv.x + rv.y*wv.y + rv.z*wv.z + rv.w*wv.w;
        }
    }
    #pragma unroll
    for (int t = 0; t < 4; t++)
        #pragma unroll
        for (int o = 16; o; o >>= 1)
            acc[t] += __shfl_xor_sync(0xFFFFFFFFu, acc[t], o);
    if (lane == 0) {
        float z[4], m = -1e30f;
        #pragma unroll
        for (int t = 0; t < 4; t++) { z[t] = acc[t] + br2[t]; m = fmaxf(m, z[t]); }
        float s = 0.0f;
        #pragma unroll
        for (int t = 0; t < 4; t++) { z[t] = expf(z[t] - m); s += z[t]; }
        float inv = 1.0f / s;
        #pragma unroll
        for (int t = 0; t < 4; t++) tw[(size_t)b * 4 + t] = z[t] * inv;
    }
}

// ---------------------------------------------------------------------------
// Salience + softmax over S=64. 1 warp per row.
// ---------------------------------------------------------------------------
__global__ void sal_softmax_kernel(const float* __restrict__ sim,
                                   const float* __restrict__ tw,
                                   float* __restrict__ attn)
{
    const int warp = threadIdx.x >> 5, lane = threadIdx.x & 31;
    const int b = blockIdx.x * 8 + warp;
    float sal[2];
    #pragma unroll
    for (int i = 0; i < 2; i++) {
        int s = lane + 32 * i;
        float v = g_wsimc[s] * tw[(size_t)b * 4 + (s >> 4)]
                * sim[(size_t)b * S_PROTO + s] + g_base[s];
        sal[i] = fminf(fmaxf(v, 0.0f), 1.0f);
    }
    float m = fmaxf(sal[0], sal[1]);
    #pragma unroll
    for (int o = 16; o; o >>= 1) m = fmaxf(m, __shfl_xor_sync(0xFFFFFFFFu, m, o));
    const float invT = 1.0f / 0.07f;
    float e0 = expf((sal[0] - m) * invT);
    float e1 = expf((sal[1] - m) * invT);
    float s = e0 + e1;
    #pragma unroll
    for (int o = 16; o; o >>= 1) s += __shfl_xor_sync(0xFFFFFFFFu, s, o);
    float inv = 1.0f / s;
    attn[(size_t)b * S_PROTO + lane]      = e0 * inv;
    attn[(size_t)b * S_PROTO + lane + 32] = e1 * inv;
}

// ---------------------------------------------------------------------------
// retrieved = attn @ prototypes, written directly as (hi, lo) bf16 split.
// ---------------------------------------------------------------------------
__global__ void retrieve_kernel(const float* __restrict__ attn,
                                const float* __restrict__ protos,
                                __nv_bfloat16* __restrict__ out_hi,
                                __nv_bfloat16* __restrict__ out_lo)
{
    __shared__ float sA[16][S_PROTO];
    const int tid = threadIdx.x;
    const int r0 = blockIdx.y * 16;
    for (int i = tid; i < 16 * S_PROTO; i += 256)
        sA[i / S_PROTO][i % S_PROTO] =
            attn[(size_t)(r0 + i / S_PROTO) * S_PROTO + (i % S_PROTO)];
    __syncthreads();

    const int n = blockIdx.x * 256 + tid;
    float acc[16];
    #pragma unroll
    for (int r = 0; r < 16; r++) acc[r] = 0.0f;
    for (int s = 0; s < S_PROTO; s++) {
        float p = protos[(size_t)s * D_DIM + n];
        #pragma unroll
        for (int r = 0; r < 16; r++) acc[r] = fmaf(sA[r][s], p, acc[r]);
    }
    #pragma unroll
    for (int r = 0; r < 16; r++) {
        float v = acc[r];
        __nv_bfloat16 h = __float2bfloat16(v);
        out_hi[(size_t)(r0 + r) * D_DIM + n] = h;
        out_lo[(size_t)(r0 + r) * D_DIM + n] = __float2bfloat16(v - __bfloat162float(h));
    }
}

// ---------------------------------------------------------------------------
// In-place LayerNorm over D
// ---------------------------------------------------------------------------
__global__ void layernorm_inplace(float* __restrict__ y,
                                  const float* __restrict__ w,
                                  const float* __restrict__ bb)
{
    const size_t base = (size_t)blockIdx.x * D_DIM;
    float4* yp = reinterpret_cast<float4*>(y + base);
    float4 v[2];
    float sum = 0.0f;
    #pragma unroll
    for (int i = 0; i < 2; i++) {
        v[i] = yp[threadIdx.x + 256 * i];
        sum += v[i].x + v[i].y + v[i].z + v[i].w;
    }
    float mu = block_reduce_sum(sum) * (1.0f / D_DIM);
    float sq = 0.0f;
    #pragma unroll
    for (int i = 0; i < 2; i++) {
        float dx = v[i].x - mu, dy = v[i].y - mu, dz = v[i].z - mu, dw = v[i].w - mu;
        sq += dx*dx + dy*dy + dz*dz + dw*dw;
    }
    float var = block_reduce_sum(sq) * (1.0f / D_DIM);
    float rstd = rsqrtf(var + 1e-5f);
    #pragma unroll
    for (int i = 0; i < 2; i++) {
        int col = (threadIdx.x + 256 * i) * 4;
        float4 wv = *reinterpret_cast<const float4*>(&w[col]);
        float4 bv = *reinterpret_cast<const float4*>(&bb[col]);
        float4 o;
        o.x = wv.x * (v[i].x - mu) * rstd + bv.x;
        o.y = wv.y * (v[i].y - mu) * rstd + bv.y;
        o.z = wv.z * (v[i].z - mu) * rstd + bv.z;
        o.w = wv.w * (v[i].w - mu) * rstd + bv.w;
        yp[threadIdx.x + 256 * i] = o;
    }
}

// ---------------------------------------------------------------------------
// Launch
// ---------------------------------------------------------------------------
extern "C" void kernel_launch(void* const* d_in, const int* in_sizes, int n_in,
                              void* d_out, int out_size)
{
    const float* x      = (const float*)d_in[0];
    const float* protos = (const float*)d_in[1];
    const float* conf   = (const float*)d_in[2];
    const float* age    = (const float*)d_in[3];
    const float* ev     = (const float*)d_in[4];
    const float* W_in   = (const float*)d_in[5];
    const float* b_in   = (const float*)d_in[6];
    const float* Wr1    = (const float*)d_in[7];
    const float* br1    = (const float*)d_in[8];
    const float* Wr2    = (const float*)d_in[9];
    const float* br2    = (const float*)d_in[10];
    const float* W_out  = (const float*)d_in[11];
    const float* b_out  = (const float*)d_in[12];
    const float* ln_w   = (const float*)d_in[13];
    const float* ln_b   = (const float*)d_in[14];
    float* out = (float*)d_out;

    __nv_bfloat16 *xhi, *xlo, *winhi, *winlo, *wr1hi, *wr1lo, *wouthi, *woutlo, *rethi, *retlo;
    float *h, *r, *tw, *sim, *attn, *pn;
    cudaGetSymbolAddress((void**)&xhi, g_x_hi);     cudaGetSymbolAddress((void**)&xlo, g_x_lo);
    cudaGetSymbolAddress((void**)&winhi, g_Win_hi); cudaGetSymbolAddress((void**)&winlo, g_Win_lo);
    cudaGetSymbolAddress((void**)&wr1hi, g_Wr1_hi); cudaGetSymbolAddress((void**)&wr1lo, g_Wr1_lo);
    cudaGetSymbolAddress((void**)&wouthi, g_Wout_hi); cudaGetSymbolAddress((void**)&woutlo, g_Wout_lo);
    cudaGetSymbolAddress((void**)&rethi, g_retr_hi); cudaGetSymbolAddress((void**)&retlo, g_retr_lo);
    cudaGetSymbolAddress((void**)&h,    g_h);
    cudaGetSymbolAddress((void**)&r,    g_r);
    cudaGetSymbolAddress((void**)&tw,   g_tw);
    cudaGetSymbolAddress((void**)&sim,  g_sim);
    cudaGetSymbolAddress((void**)&attn, g_attn);
    cudaGetSymbolAddress((void**)&pn,   g_pn);

    constexpr int SMEM_SZ = 3 * 4 * 128 * 32 * 2;  // 98304 bytes
    cudaFuncSetAttribute(mma_gemm<0>, cudaFuncAttributeMaxDynamicSharedMemorySize, SMEM_SZ);
    cudaFuncSetAttribute(mma_gemm<1>, cudaFuncAttributeMaxDynamicSharedMemorySize, SMEM_SZ);
    cudaFuncSetAttribute(mma_gemm<7>, cudaFuncAttributeMaxDynamicSharedMemorySize, SMEM_SZ);

    const int B = B_ROWS;

    // bf16 hi/lo splits of x and weights
    {
        size_t n4;
        n4 = (size_t)B * D_DIM / 4;
        split_kernel<<<(unsigned)((n4 + 255) / 256), 256>>>(x, xhi, xlo, n4);
        n4 = (size_t)D_DIM * D_DIM / 4;
        split_kernel<<<(unsigned)((n4 + 255) / 256), 256>>>(W_in, winhi, winlo, n4);
        n4 = (size_t)D_HALF * D_DIM / 4;
        split_kernel<<<(unsigned)((n4 + 255) / 256), 256>>>(Wr1, wr1hi, wr1lo, n4);
        n4 = (size_t)D_DIM * 2 * D_DIM / 4;
        split_kernel<<<(unsigned)((n4 + 255) / 256), 256>>>(W_out, wouthi, woutlo, n4);
    }

    // G1: h = x @ W_in^T + b_in
    mma_gemm<0><<<dim3(D_DIM / 128, B / 128), 256, SMEM_SZ>>>(
        xhi, xlo, nullptr, nullptr, winhi, winlo, b_in, nullptr, h,
        B, D_DIM, D_DIM, 0, D_DIM);

    // G2: r = gelu(x @ Wr1^T + br1)
    mma_gemm<1><<<dim3(D_HALF / 128, B / 128), 256, SMEM_SZ>>>(
        xhi, xlo, nullptr, nullptr, wr1hi, wr1lo, br1, nullptr, r,
        B, D_HALF, D_DIM, 0, D_DIM);

    type_weights_kernel<<<B / 8, 256>>>(r, Wr2, br2, tw);
    proto_prep<<<S_PROTO, 256>>>(protos, conf, age, ev);
    rownorm_inplace<<<B, 256>>>(h);

    // sim = h_norm @ p_norm^T  (SIMT; tiny FLOPs)
    gemm_nt<128, 64, 16, 8, 4><<<dim3(1, B / 128), 256>>>(
        h, pn, sim, B, S_PROTO, D_DIM);

    sal_softmax_kernel<<<B / 8, 256>>>(sim, tw, attn);

    // retrieved (written as bf16 hi/lo split)
    retrieve_kernel<<<dim3(D_DIM / 256, B / 16), 256>>>(attn, protos, rethi, retlo);

    // G3: out = gelu([x, retrieved] @ W_out^T + b_out) + x
    mma_gemm<7><<<dim3(D_DIM / 128, B / 128), 256, SMEM_SZ>>>(
        xhi, xlo, rethi, retlo, wouthi, woutlo, b_out, x, out,
        B, D_DIM, 2 * D_DIM, D_DIM, D_DIM);

    layernorm_inplace<<<B, 256>>>(out, ln_w, ln_b);
}

// round 4
// speedup vs baseline: 2.8856x; 1.1436x over previous
#include <cuda_runtime.h>
#include <cuda_bf16.h>
#include <math.h>
#include <stdint.h>

#define B_ROWS 16384
#define D_DIM  2048
#define D_HALF 1024
#define S_PROTO 64

// ---------------------------------------------------------------------------
// Scratch (device globals; allocation-free per harness rules)
// ---------------------------------------------------------------------------
__device__ __nv_bfloat16 g_x_hi[(size_t)B_ROWS * D_DIM];
__device__ __nv_bfloat16 g_x_lo[(size_t)B_ROWS * D_DIM];
__device__ __nv_bfloat16 g_Win_hi[(size_t)D_DIM * D_DIM];
__device__ __nv_bfloat16 g_Win_lo[(size_t)D_DIM * D_DIM];
__device__ __nv_bfloat16 g_Wr1_hi[(size_t)D_HALF * D_DIM];
__device__ __nv_bfloat16 g_Wr1_lo[(size_t)D_HALF * D_DIM];
__device__ __nv_bfloat16 g_Wout_hi[(size_t)D_DIM * 2 * D_DIM];
__device__ __nv_bfloat16 g_Wout_lo[(size_t)D_DIM * 2 * D_DIM];
__device__ __nv_bfloat16 g_retr_hi[(size_t)B_ROWS * D_DIM];
__device__ __nv_bfloat16 g_retr_lo[(size_t)B_ROWS * D_DIM];
__device__ float g_h[(size_t)B_ROWS * D_DIM];
__device__ float g_r[(size_t)B_ROWS * D_HALF];
__device__ float g_tw[(size_t)B_ROWS * 4];
__device__ float g_attn[(size_t)B_ROWS * S_PROTO];
__device__ float g_pn[(size_t)S_PROTO * D_DIM];
__device__ float g_base[S_PROTO];
__device__ float g_wsimc[S_PROTO];

// ---------------------------------------------------------------------------
// PTX helpers (baseline ISA: mma.sync / ldmatrix / cp.async)
// ---------------------------------------------------------------------------
__device__ __forceinline__ uint32_t smem_to_u32(const void* p) {
    uint32_t a;
    asm("{ .reg .u64 t; cvta.to.shared.u64 t, %1; cvt.u32.u64 %0, t; }"
        : "=r"(a) : "l"(p));
    return a;
}

__device__ __forceinline__ void cpasync16(uint32_t saddr, const void* g) {
    asm volatile("cp.async.cg.shared.global [%0], [%1], 16;"
                 :: "r"(saddr), "l"(g));
}
#define CP_COMMIT() asm volatile("cp.async.commit_group;" ::: "memory")
#define CP_WAIT(n)  asm volatile("cp.async.wait_group %0;" :: "n"(n) : "memory")

__device__ __forceinline__ void ldsm4(uint32_t* r, uint32_t addr) {
    asm volatile("ldmatrix.sync.aligned.m8n8.x4.shared.b16 {%0,%1,%2,%3}, [%4];"
                 : "=r"(r[0]), "=r"(r[1]), "=r"(r[2]), "=r"(r[3]) : "r"(addr));
}

__device__ __forceinline__ void mma_bf16(float* d, const uint32_t* a, const uint32_t* b) {
    asm volatile(
        "mma.sync.aligned.m16n8k16.row.col.f32.bf16.bf16.f32 "
        "{%0,%1,%2,%3}, {%4,%5,%6,%7}, {%8,%9}, {%0,%1,%2,%3};"
        : "+f"(d[0]), "+f"(d[1]), "+f"(d[2]), "+f"(d[3])
        : "r"(a[0]), "r"(a[1]), "r"(a[2]), "r"(a[3]), "r"(b[0]), "r"(b[1]));
}

// ---------------------------------------------------------------------------
// Misc helpers
// ---------------------------------------------------------------------------
__device__ __forceinline__ float gelu_exact(float v) {
    return 0.5f * v * (1.0f + erff(v * 0.70710678118654752440f));
}

__device__ __forceinline__ float block_reduce_sum(float v) {
    __shared__ float sh[32];
    int lane = threadIdx.x & 31, w = threadIdx.x >> 5;
    #pragma unroll
    for (int o = 16; o; o >>= 1) v += __shfl_xor_sync(0xFFFFFFFFu, v, o);
    if (lane == 0) sh[w] = v;
    __syncthreads();
    float r = (threadIdx.x < (blockDim.x >> 5)) ? sh[threadIdx.x] : 0.0f;
    if (w == 0) {
        #pragma unroll
        for (int o = 16; o; o >>= 1) r += __shfl_xor_sync(0xFFFFFFFFu, r, o);
        if (lane == 0) sh[0] = r;
    }
    __syncthreads();
    float out = sh[0];
    __syncthreads();
    return out;
}

// ---------------------------------------------------------------------------
// fp32 -> (bf16 hi, bf16 lo) split
// ---------------------------------------------------------------------------
__device__ __forceinline__ void split2(float a, float b, uint32_t& hi, uint32_t& lo) {
    __nv_bfloat162 h = __floats2bfloat162_rn(a, b);
    float2 hf = __bfloat1622float2(h);
    __nv_bfloat162 l = __floats2bfloat162_rn(a - hf.x, b - hf.y);
    hi = *reinterpret_cast<uint32_t*>(&h);
    lo = *reinterpret_cast<uint32_t*>(&l);
}

__global__ void split_kernel(const float* __restrict__ s,
                             __nv_bfloat16* __restrict__ hi,
                             __nv_bfloat16* __restrict__ lo, size_t n4)
{
    size_t i = (size_t)blockIdx.x * blockDim.x + threadIdx.x;
    if (i >= n4) return;
    float4 v = reinterpret_cast<const float4*>(s)[i];
    uint2 ph, pl;
    split2(v.x, v.y, ph.x, pl.x);
    split2(v.z, v.w, ph.y, pl.y);
    reinterpret_cast<uint2*>(hi)[i] = ph;
    reinterpret_cast<uint2*>(lo)[i] = pl;
}

// ---------------------------------------------------------------------------
// HMMA (mma.sync bf16, 3-pass split) GEMM.
// MODE bits: 1=gelu, 2=+Xres, 4=split-A, 8=dual-output (second matrix set
//   for blocks with blockIdx.x >= NXtiles; second output always gelu).
// BM=BN=128, BK=32, 3-stage cp.async, 256 threads, 2 CTAs/SM target.
// ---------------------------------------------------------------------------
template<int MODE>
__global__ void __launch_bounds__(256, 2)
mma_gemm(const __nv_bfloat16* __restrict__ Ahi, const __nv_bfloat16* __restrict__ Alo,
         const __nv_bfloat16* __restrict__ A2hi, const __nv_bfloat16* __restrict__ A2lo,
         const __nv_bfloat16* __restrict__ Bhi, const __nv_bfloat16* __restrict__ Blo,
         const float* __restrict__ bias, const float* __restrict__ Xres,
         float* __restrict__ C, int N, int K, int Ksplit, int strideA,
         const __nv_bfloat16* __restrict__ B2hi, const __nv_bfloat16* __restrict__ B2lo,
         const float* __restrict__ bias2, float* __restrict__ C2, int N2, int NXtiles)
{
    constexpr int BM = 128, BK = 32, STAGES = 3;
    constexpr int TILE_B  = BM * BK * 2;      // 8192 bytes
    constexpr int STAGE_B = 4 * TILE_B;

    extern __shared__ __align__(16) char smem[];
    const uint32_t sbase = smem_to_u32(smem);

    const int tid  = threadIdx.x;
    const int wid  = tid >> 5, lane = tid & 31;
    const int m0 = blockIdx.y * BM;

    int bx = blockIdx.x;
    bool second = false;
    if constexpr (MODE & 8) {
        if (bx >= NXtiles) { second = true; bx -= NXtiles; }
    }
    const __nv_bfloat16* pBhi = second ? B2hi : Bhi;
    const __nv_bfloat16* pBlo = second ? B2lo : Blo;
    const float* pbias = second ? bias2 : bias;
    float* pC = second ? C2 : C;
    const int NN = second ? N2 : N;
    const int n0 = bx * BM;
    const bool do_gelu = (MODE & 1) || second;

    const int wm = (wid >> 2) * 64;
    const int wn = (wid & 3) * 32;

    float acc[4][4][4];
    #pragma unroll
    for (int i = 0; i < 4; i++)
        #pragma unroll
        for (int j = 0; j < 4; j++)
            #pragma unroll
            for (int k = 0; k < 4; k++) acc[i][j][k] = 0.0f;

    const int nk = K / BK;

    auto load_stage = [&](int s, int t) {
        const int k0 = t * BK;
        const __nv_bfloat16 *pAh = Ahi, *pAl = Alo;
        int ka = k0;
        if constexpr (MODE & 4) {
            if (k0 >= Ksplit) { pAh = A2hi; pAl = A2lo; ka = k0 - Ksplit; }
        }
        const uint32_t sb = sbase + s * STAGE_B;
        #pragma unroll
        for (int i = 0; i < 2; i++) {
            int idx = tid + i * 256;
            int row = idx >> 2, g = idx & 3;
            int gs  = g ^ (row & 3);
            uint32_t so = row * 64 + gs * 16;
            size_t ga = (size_t)(m0 + row) * strideA + ka + g * 8;
            size_t gb = (size_t)(n0 + row) * K + k0 + g * 8;
            cpasync16(sb + 0 * TILE_B + so, pAh + ga);
            cpasync16(sb + 1 * TILE_B + so, pAl + ga);
            cpasync16(sb + 2 * TILE_B + so, pBhi + gb);
            cpasync16(sb + 3 * TILE_B + so, pBlo + gb);
        }
    };

    auto compute_stage = [&](int s) {
        const uint32_t sb = sbase + s * STAGE_B;
        #pragma unroll
        for (int ks = 0; ks < 2; ks++) {
            uint32_t aaddr[4], baddr[2];
            #pragma unroll
            for (int mf = 0; mf < 4; mf++) {
                int row = wm + mf * 16 + (lane & 15);
                int g   = ks * 2 + (lane >> 4);
                aaddr[mf] = sb + row * 64 + ((g ^ (row & 3)) * 16);
            }
            #pragma unroll
            for (int nf2 = 0; nf2 < 2; nf2++) {
                int nrow = wn + nf2 * 16 + ((lane >> 4) & 1) * 8 + (lane & 7);
                int g    = ks * 2 + ((lane >> 3) & 1);
                baddr[nf2] = sb + 2 * TILE_B + nrow * 64 + ((g ^ (nrow & 3)) * 16);
            }
            // pass 1: hi * hi
            uint32_t ahi[4][4], bfr[2][4];
            #pragma unroll
            for (int mf = 0; mf < 4; mf++) ldsm4(ahi[mf], aaddr[mf]);
            #pragma unroll
            for (int nf2 = 0; nf2 < 2; nf2++) ldsm4(bfr[nf2], baddr[nf2]);
            #pragma unroll
            for (int mf = 0; mf < 4; mf++)
                #pragma unroll
                for (int nf = 0; nf < 4; nf++)
                    mma_bf16(acc[mf][nf], ahi[mf], &bfr[nf >> 1][(nf & 1) * 2]);
            // pass 2: lo(A) * hi(B)   (bfr still holds Bhi)
            {
                uint32_t alo[4][4];
                #pragma unroll
                for (int mf = 0; mf < 4; mf++) ldsm4(alo[mf], aaddr[mf] + TILE_B);
                #pragma unroll
                for (int mf = 0; mf < 4; mf++)
                    #pragma unroll
                    for (int nf = 0; nf < 4; nf++)
                        mma_bf16(acc[mf][nf], alo[mf], &bfr[nf >> 1][(nf & 1) * 2]);
            }
            // pass 3: hi(A) * lo(B)   (overwrite bfr with Blo)
            #pragma unroll
            for (int nf2 = 0; nf2 < 2; nf2++) ldsm4(bfr[nf2], baddr[nf2] + TILE_B);
            #pragma unroll
            for (int mf = 0; mf < 4; mf++)
                #pragma unroll
                for (int nf = 0; nf < 4; nf++)
                    mma_bf16(acc[mf][nf], ahi[mf], &bfr[nf >> 1][(nf & 1) * 2]);
        }
    };

    load_stage(0, 0); CP_COMMIT();
    load_stage(1, 1); CP_COMMIT();

    for (int t = 0; t < nk; t++) {
        CP_WAIT(STAGES - 2);
        __syncthreads();
        if (t + STAGES - 1 < nk) load_stage((t + STAGES - 1) % STAGES, t + STAGES - 1);
        CP_COMMIT();
        compute_stage(t % STAGES);
    }

    #pragma unroll
    for (int mf = 0; mf < 4; mf++)
        #pragma unroll
        for (int nf = 0; nf < 4; nf++)
            #pragma unroll
            for (int half = 0; half < 2; half++) {
                int row = m0 + wm + mf * 16 + (lane >> 2) + half * 8;
                int col = n0 + wn + nf * 8 + (lane & 3) * 2;
                float v0 = acc[mf][nf][half * 2 + 0] + pbias[col];
                float v1 = acc[mf][nf][half * 2 + 1] + pbias[col + 1];
                if (do_gelu) { v0 = gelu_exact(v0); v1 = gelu_exact(v1); }
                if constexpr (MODE & 2) {
                    float2 xr = *reinterpret_cast<const float2*>(
                        &Xres[(size_t)row * NN + col]);
                    v0 += xr.x; v1 += xr.y;
                }
                float2 o; o.x = v0; o.y = v1;
                *reinterpret_cast<float2*>(&pC[(size_t)row * NN + col]) = o;
            }
}

// ---------------------------------------------------------------------------
// Fused: row-norms of h + sim GEMM (h @ pn^T) + salience + softmax -> attn
// BM=128, BN=64 (= S), BK=16, 256 threads, fp32 SIMT.
// ---------------------------------------------------------------------------
__global__ void __launch_bounds__(256)
sim_attn_kernel(const float* __restrict__ A, const float* __restrict__ Bm,
                const float* __restrict__ tw, float* __restrict__ attn)
{
    constexpr int BM = 128, BN = 64, BK = 16, TM = 8, TN = 4, PAD = 4;
    constexpr int KV = BK / 4;
    constexpr int AS_B = 2 * BK * (BM + PAD) * 4;   // 16896
    constexpr int SAL_OFF = 0;                       // overlays As/Bs post-compute
    constexpr int SSQ_OFF = 33280;

    extern __shared__ __align__(16) char dsm[];
    float (*As)[BK][BM + PAD] = reinterpret_cast<float (*)[BK][BM + PAD]>(dsm);
    float (*Bs)[BK][BN + PAD] = reinterpret_cast<float (*)[BK][BN + PAD]>(dsm + AS_B);
    float* sal = reinterpret_cast<float*>(dsm + SAL_OFF);
    float* ssq_sm = reinterpret_cast<float*>(dsm + SSQ_OFF);

    const int tid = threadIdx.x;
    const int m0 = blockIdx.y * BM;
    const int tr = tid / 16;          // 0..15
    const int tc = tid % 16;

    const int K = D_DIM;
    float4 aReg[2]; float4 bReg;
    float acc[TM][TN];
    float ssq[2] = {0.f, 0.f};
    #pragma unroll
    for (int i = 0; i < TM; i++)
        #pragma unroll
        for (int j = 0; j < TN; j++) acc[i][j] = 0.0f;

    auto fetch = [&](int kt) {
        #pragma unroll
        for (int i = 0; i < 2; i++) {
            int idx = tid + i * 256;
            int row = idx / KV, kc = (idx % KV) * 4;
            aReg[i] = *reinterpret_cast<const float4*>(A + (size_t)(m0+row)*K + kt + kc);
            ssq[i] += aReg[i].x*aReg[i].x + aReg[i].y*aReg[i].y
                    + aReg[i].z*aReg[i].z + aReg[i].w*aReg[i].w;
        }
        {
            int row = tid / KV, kc = (tid % KV) * 4;
            bReg = *reinterpret_cast<const float4*>(Bm + (size_t)row*K + kt + kc);
        }
    };
    auto stash = [&](int buf) {
        #pragma unroll
        for (int i = 0; i < 2; i++) {
            int idx = tid + i * 256;
            int row = idx / KV, kc = (idx % KV) * 4;
            As[buf][kc+0][row] = aReg[i].x; As[buf][kc+1][row] = aReg[i].y;
            As[buf][kc+2][row] = aReg[i].z; As[buf][kc+3][row] = aReg[i].w;
        }
        {
            int row = tid / KV, kc = (tid % KV) * 4;
            Bs[buf][kc+0][row] = bReg.x; Bs[buf][kc+1][row] = bReg.y;
            Bs[buf][kc+2][row] = bReg.z; Bs[buf][kc+3][row] = bReg.w;
        }
    };

    fetch(0); stash(0);
    __syncthreads();

    const int nk = K / BK;
    for (int t = 0; t < nk; t++) {
        const int cur = t & 1;
        if (t + 1 < nk) fetch((t + 1) * BK);
        #pragma unroll
        for (int k = 0; k < BK; k++) {
            float a[TM], b[TN];
            #pragma unroll
            for (int i = 0; i < TM; i += 4) {
                float4 v = *reinterpret_cast<const float4*>(&As[cur][k][tr*TM + i]);
                a[i]=v.x; a[i+1]=v.y; a[i+2]=v.z; a[i+3]=v.w;
            }
            #pragma unroll
            for (int j = 0; j < TN; j += 4) {
                float4 v = *reinterpret_cast<const float4*>(&Bs[cur][k][tc*TN + j]);
                b[j]=v.x; b[j+1]=v.y; b[j+2]=v.z; b[j+3]=v.w;
            }
            #pragma unroll
            for (int i = 0; i < TM; i++)
                #pragma unroll
                for (int j = 0; j < TN; j++)
                    acc[i][j] = fmaf(a[i], b[j], acc[i][j]);
        }
        if (t + 1 < nk) stash(cur ^ 1);
        __syncthreads();
    }

    // per-row sum of squares: threads 4q..4q+3 share row q (and q+64)
    #pragma unroll
    for (int i = 0; i < 2; i++) {
        ssq[i] += __shfl_xor_sync(0xFFFFFFFFu, ssq[i], 1);
        ssq[i] += __shfl_xor_sync(0xFFFFFFFFu, ssq[i], 2);
    }
    if ((tid & 3) == 0) {
        ssq_sm[tid / 4]      = ssq[0];
        ssq_sm[64 + tid / 4] = ssq[1];
    }
    __syncthreads();   // ssq ready; all compute done -> safe to overlay sal

    // salience (clip 0..1) into smem
    const float twv_base_idx = 0.0f; (void)twv_base_idx;
    #pragma unroll
    for (int i = 0; i < TM; i++) {
        int row = tr * TM + i;
        float invn = 1.0f / fmaxf(sqrtf(ssq_sm[row]), 1e-12f);
        float twv = tw[(size_t)(m0 + row) * 4 + (tc >> 2)];
        #pragma unroll
        for (int j = 0; j < TN; j++) {
            int col = tc * TN + j;
            float v = g_wsimc[col] * twv * (acc[i][j] * invn) + g_base[col];
            sal[row * 65 + col] = fminf(fmaxf(v, 0.0f), 1.0f);
        }
    }
    __syncthreads();

    // softmax over 64 per row; 2 threads per row
    {
        int row = tid >> 1, half = tid & 1;
        const float* srow = &sal[row * 65 + half * 32];
        float m = -1e30f;
        #pragma unroll
        for (int c = 0; c < 32; c++) m = fmaxf(m, srow[c]);
        m = fmaxf(m, __shfl_xor_sync(0xFFFFFFFFu, m, 1));
        const float invT = 1.0f / 0.07f;
        float e[32], s = 0.0f;
        #pragma unroll
        for (int c = 0; c < 32; c++) { e[c] = expf((srow[c] - m) * invT); s += e[c]; }
        s += __shfl_xor_sync(0xFFFFFFFFu, s, 1);
        float inv = 1.0f / s;
        float* dst = &attn[(size_t)(m0 + row) * S_PROTO + half * 32];
        #pragma unroll
        for (int c = 0; c < 32; c += 4) {
            float4 o; o.x = e[c]*inv; o.y = e[c+1]*inv; o.z = e[c+2]*inv; o.w = e[c+3]*inv;
            *reinterpret_cast<float4*>(dst + c) = o;
        }
    }
}

// ---------------------------------------------------------------------------
// Prototype prep
// ---------------------------------------------------------------------------
__global__ void proto_prep(const float* __restrict__ protos,
                           const float* __restrict__ conf,
                           const float* __restrict__ age,
                           const float* __restrict__ ev)
{
    const int s = blockIdx.x;
    float ss = 0.0f;
    for (int k = threadIdx.x; k < D_DIM; k += 256) {
        float v = protos[(size_t)s * D_DIM + k];
        ss += v * v;
    }
    float tot = block_reduce_sum(ss);
    float scale = 1.0f / fmaxf(sqrtf(tot), 1e-12f);
    for (int k = threadIdx.x; k < D_DIM; k += 256)
        g_pn[(size_t)s * D_DIM + k] = protos[(size_t)s * D_DIM + k] * scale;

    if (threadIdx.x == 0) {
        float evmax = 0.0f;
        for (int i = 0; i < S_PROTO; i++) evmax = fmaxf(evmax, ev[i]);
        float freq = logf(ev[s] + 1.0f) / (logf(evmax + 2.0f) + 1e-8f);
        float rec  = expf(-age[s] * (1.0f / 200.0f));
        g_base[s]  = 0.2f * rec + 0.15f * freq + 0.1f * conf[s] + 0.1f * 0.9f;
        g_wsimc[s] = 0.45f * conf[s];
    }
}

// ---------------------------------------------------------------------------
// Type weights softmax (4 logits). 1 warp per row.
// ---------------------------------------------------------------------------
__global__ void type_weights_kernel(const float* __restrict__ r,
                                    const float* __restrict__ Wr2,
                                    const float* __restrict__ br2,
                                    float* __restrict__ tw)
{
    const int warp = threadIdx.x >> 5, lane = threadIdx.x & 31;
    const int b = blockIdx.x * 8 + warp;
    const float4* rp = reinterpret_cast<const float4*>(r + (size_t)b * D_HALF);
    float acc[4] = {0.f, 0.f, 0.f, 0.f};
    for (int i = lane; i < D_HALF / 4; i += 32) {
        float4 rv = rp[i];
        #pragma unroll
        for (int t = 0; t < 4; t++) {
            float4 wv = reinterpret_cast<const float4*>(Wr2 + (size_t)t * D_HALF)[i];
            acc[t] += rv.x*wv.x + rv.y*wv.y + rv.z*wv.z + rv.w*wv.w;
        }
    }
    #pragma unroll
    for (int t = 0; t < 4; t++)
        #pragma unroll
        for (int o = 16; o; o >>= 1)
            acc[t] += __shfl_xor_sync(0xFFFFFFFFu, acc[t], o);
    if (lane == 0) {
        float z[4], m = -1e30f;
        #pragma unroll
        for (int t = 0; t < 4; t++) { z[t] = acc[t] + br2[t]; m = fmaxf(m, z[t]); }
        float s = 0.0f;
        #pragma unroll
        for (int t = 0; t < 4; t++) { z[t] = expf(z[t] - m); s += z[t]; }
        float inv = 1.0f / s;
        #pragma unroll
        for (int t = 0; t < 4; t++) tw[(size_t)b * 4 + t] = z[t] * inv;
    }
}

// ---------------------------------------------------------------------------
// retrieved = attn @ prototypes, written as (hi, lo) bf16 split.
// ---------------------------------------------------------------------------
__global__ void retrieve_kernel(const float* __restrict__ attn,
                                const float* __restrict__ protos,
                                __nv_bfloat16* __restrict__ out_hi,
                                __nv_bfloat16* __restrict__ out_lo)
{
    __shared__ float sA[16][S_PROTO];
    const int tid = threadIdx.x;
    const int r0 = blockIdx.y * 16;
    for (int i = tid; i < 16 * S_PROTO; i += 256)
        sA[i / S_PROTO][i % S_PROTO] =
            attn[(size_t)(r0 + i / S_PROTO) * S_PROTO + (i % S_PROTO)];
    __syncthreads();

    const int n = blockIdx.x * 256 + tid;
    float acc[16];
    #pragma unroll
    for (int r = 0; r < 16; r++) acc[r] = 0.0f;
    for (int s = 0; s < S_PROTO; s++) {
        float p = protos[(size_t)s * D_DIM + n];
        #pragma unroll
        for (int r = 0; r < 16; r++) acc[r] = fmaf(sA[r][s], p, acc[r]);
    }
    #pragma unroll
    for (int r = 0; r < 16; r++) {
        float v = acc[r];
        __nv_bfloat16 h = __float2bfloat16(v);
        out_hi[(size_t)(r0 + r) * D_DIM + n] = h;
        out_lo[(size_t)(r0 + r) * D_DIM + n] = __float2bfloat16(v - __bfloat162float(h));
    }
}

// ---------------------------------------------------------------------------
// In-place LayerNorm over D
// ---------------------------------------------------------------------------
__global__ void layernorm_inplace(float* __restrict__ y,
                                  const float* __restrict__ w,
                                  const float* __restrict__ bb)
{
    const size_t base = (size_t)blockIdx.x * D_DIM;
    float4* yp = reinterpret_cast<float4*>(y + base);
    float4 v[2];
    float sum = 0.0f;
    #pragma unroll
    for (int i = 0; i < 2; i++) {
        v[i] = yp[threadIdx.x + 256 * i];
        sum += v[i].x + v[i].y + v[i].z + v[i].w;
    }
    float mu = block_reduce_sum(sum) * (1.0f / D_DIM);
    float sq = 0.0f;
    #pragma unroll
    for (int i = 0; i < 2; i++) {
        float dx = v[i].x - mu, dy = v[i].y - mu, dz = v[i].z - mu, dw = v[i].w - mu;
        sq += dx*dx + dy*dy + dz*dz + dw*dw;
    }
    float var = block_reduce_sum(sq) * (1.0f / D_DIM);
    float rstd = rsqrtf(var + 1e-5f);
    #pragma unroll
    for (int i = 0; i < 2; i++) {
        int col = (threadIdx.x + 256 * i) * 4;
        float4 wv = *reinterpret_cast<const float4*>(&w[col]);
        float4 bv = *reinterpret_cast<const float4*>(&bb[col]);
        float4 o;
        o.x = wv.x * (v[i].x - mu) * rstd + bv.x;
        o.y = wv.y * (v[i].y - mu) * rstd + bv.y;
        o.z = wv.z * (v[i].z - mu) * rstd + bv.z;
        o.w = wv.w * (v[i].w - mu) * rstd + bv.w;
        yp[threadIdx.x + 256 * i] = o;
    }
}

// ---------------------------------------------------------------------------
// Launch
// ---------------------------------------------------------------------------
extern "C" void kernel_launch(void* const* d_in, const int* in_sizes, int n_in,
                              void* d_out, int out_size)
{
    const float* x      = (const float*)d_in[0];
    const float* protos = (const float*)d_in[1];
    const float* conf   = (const float*)d_in[2];
    const float* age    = (const float*)d_in[3];
    const float* ev     = (const float*)d_in[4];
    const float* W_in   = (const float*)d_in[5];
    const float* b_in   = (const float*)d_in[6];
    const float* Wr1    = (const float*)d_in[7];
    const float* br1    = (const float*)d_in[8];
    const float* Wr2    = (const float*)d_in[9];
    const float* br2    = (const float*)d_in[10];
    const float* W_out  = (const float*)d_in[11];
    const float* b_out  = (const float*)d_in[12];
    const float* ln_w   = (const float*)d_in[13];
    const float* ln_b   = (const float*)d_in[14];
    float* out = (float*)d_out;

    __nv_bfloat16 *xhi, *xlo, *winhi, *winlo, *wr1hi, *wr1lo, *wouthi, *woutlo, *rethi, *retlo;
    float *h, *r, *tw, *attn, *pn;
    cudaGetSymbolAddress((void**)&xhi, g_x_hi);     cudaGetSymbolAddress((void**)&xlo, g_x_lo);
    cudaGetSymbolAddress((void**)&winhi, g_Win_hi); cudaGetSymbolAddress((void**)&winlo, g_Win_lo);
    cudaGetSymbolAddress((void**)&wr1hi, g_Wr1_hi); cudaGetSymbolAddress((void**)&wr1lo, g_Wr1_lo);
    cudaGetSymbolAddress((void**)&wouthi, g_Wout_hi); cudaGetSymbolAddress((void**)&woutlo, g_Wout_lo);
    cudaGetSymbolAddress((void**)&rethi, g_retr_hi); cudaGetSymbolAddress((void**)&retlo, g_retr_lo);
    cudaGetSymbolAddress((void**)&h,    g_h);
    cudaGetSymbolAddress((void**)&r,    g_r);
    cudaGetSymbolAddress((void**)&tw,   g_tw);
    cudaGetSymbolAddress((void**)&attn, g_attn);
    cudaGetSymbolAddress((void**)&pn,   g_pn);

    constexpr int SMEM_SZ = 3 * 4 * 128 * 32 * 2;   // 98304 bytes
    cudaFuncSetAttribute(mma_gemm<8>, cudaFuncAttributeMaxDynamicSharedMemorySize, SMEM_SZ);
    cudaFuncSetAttribute(mma_gemm<7>, cudaFuncAttributeMaxDynamicSharedMemorySize, SMEM_SZ);

    const int B = B_ROWS;

    // bf16 hi/lo splits of x and weights
    {
        size_t n4;
        n4 = (size_t)B * D_DIM / 4;
        split_kernel<<<(unsigned)((n4 + 255) / 256), 256>>>(x, xhi, xlo, n4);
        n4 = (size_t)D_DIM * D_DIM / 4;
        split_kernel<<<(unsigned)((n4 + 255) / 256), 256>>>(W_in, winhi, winlo, n4);
        n4 = (size_t)D_HALF * D_DIM / 4;
        split_kernel<<<(unsigned)((n4 + 255) / 256), 256>>>(Wr1, wr1hi, wr1lo, n4);
        n4 = (size_t)D_DIM * 2 * D_DIM / 4;
        split_kernel<<<(unsigned)((n4 + 255) / 256), 256>>>(W_out, wouthi, woutlo, n4);
    }

    proto_prep<<<S_PROTO, 256>>>(protos, conf, age, ev);

    // G1+G2 fused: h = x@W_in^T + b_in ; r = gelu(x@Wr1^T + br1)
    mma_gemm<8><<<dim3(D_DIM / 128 + D_HALF / 128, B / 128), 256, SMEM_SZ>>>(
        xhi, xlo, nullptr, nullptr, winhi, winlo, b_in, nullptr, h,
        D_DIM, D_DIM, 0, D_DIM,
        wr1hi, wr1lo, br1, r, D_HALF, D_DIM / 128);

    type_weights_kernel<<<B / 8, 256>>>(r, Wr2, br2, tw);

    // fused rownorm + sim + salience + softmax -> attn
    sim_attn_kernel<<<dim3(1, B / 128), 256, 33792>>>(h, pn, tw, attn);

    // retrieved (bf16 hi/lo)
    retrieve_kernel<<<dim3(D_DIM / 256, B / 16), 256>>>(attn, protos, rethi, retlo);

    // G3: out = gelu([x, retrieved] @ W_out^T + b_out) + x
    mma_gemm<7><<<dim3(D_DIM / 128, B / 128), 256, SMEM_SZ>>>(
        xhi, xlo, rethi, retlo, wouthi, woutlo, b_out, x, out,
        D_DIM, 2 * D_DIM, D_DIM, D_DIM,
        nullptr, nullptr, nullptr, nullptr, 0, 0x7FFFFFFF);

    layernorm_inplace<<<B, 256>>>(out, ln_w, ln_b);
}

// round 5
// speedup vs baseline: 7.2246x; 2.5037x over previous
#include <cuda_runtime.h>
#include <cuda_fp16.h>
#include <math.h>
#include <stdint.h>

#define B_ROWS 16384
#define D_DIM  2048
#define D_HALF 1024
#define S_PROTO 64

// ---------------------------------------------------------------------------
// Scratch (device globals; allocation-free per harness rules)
// ---------------------------------------------------------------------------
__device__ __half g_x_h[(size_t)B_ROWS * D_DIM];
__device__ __half g_Win_h[(size_t)D_DIM * D_DIM];
__device__ __half g_Wr1_h[(size_t)D_HALF * D_DIM];
__device__ __half g_Wout_h[(size_t)D_DIM * 2 * D_DIM];
__device__ __half g_retr_h[(size_t)B_ROWS * D_DIM];
__device__ float g_h[(size_t)B_ROWS * D_DIM];
__device__ float g_r[(size_t)B_ROWS * D_HALF];
__device__ float g_tw[(size_t)B_ROWS * 4];
__device__ float g_attn[(size_t)B_ROWS * S_PROTO];
__device__ float g_pn[(size_t)S_PROTO * D_DIM];
__device__ float g_base[S_PROTO];
__device__ float g_wsimc[S_PROTO];

// ---------------------------------------------------------------------------
// PTX helpers (baseline ISA: mma.sync / ldmatrix / cp.async)
// ---------------------------------------------------------------------------
__device__ __forceinline__ uint32_t smem_to_u32(const void* p) {
    uint32_t a;
    asm("{ .reg .u64 t; cvta.to.shared.u64 t, %1; cvt.u32.u64 %0, t; }"
        : "=r"(a) : "l"(p));
    return a;
}

__device__ __forceinline__ void cpasync16(uint32_t saddr, const void* g) {
    asm volatile("cp.async.cg.shared.global [%0], [%1], 16;"
                 :: "r"(saddr), "l"(g));
}
#define CP_COMMIT() asm volatile("cp.async.commit_group;" ::: "memory")
#define CP_WAIT(n)  asm volatile("cp.async.wait_group %0;" :: "n"(n) : "memory")

__device__ __forceinline__ void ldsm4(uint32_t* r, uint32_t addr) {
    asm volatile("ldmatrix.sync.aligned.m8n8.x4.shared.b16 {%0,%1,%2,%3}, [%4];"
                 : "=r"(r[0]), "=r"(r[1]), "=r"(r[2]), "=r"(r[3]) : "r"(addr));
}

__device__ __forceinline__ void mma_f16(float* d, const uint32_t* a, const uint32_t* b) {
    asm volatile(
        "mma.sync.aligned.m16n8k16.row.col.f32.f16.f16.f32 "
        "{%0,%1,%2,%3}, {%4,%5,%6,%7}, {%8,%9}, {%0,%1,%2,%3};"
        : "+f"(d[0]), "+f"(d[1]), "+f"(d[2]), "+f"(d[3])
        : "r"(a[0]), "r"(a[1]), "r"(a[2]), "r"(a[3]), "r"(b[0]), "r"(b[1]));
}

// ---------------------------------------------------------------------------
// Misc helpers
// ---------------------------------------------------------------------------
__device__ __forceinline__ float gelu_exact(float v) {
    return 0.5f * v * (1.0f + erff(v * 0.70710678118654752440f));
}

__device__ __forceinline__ float block_reduce_sum(float v) {
    __shared__ float sh[32];
    int lane = threadIdx.x & 31, w = threadIdx.x >> 5;
    #pragma unroll
    for (int o = 16; o; o >>= 1) v += __shfl_xor_sync(0xFFFFFFFFu, v, o);
    if (lane == 0) sh[w] = v;
    __syncthreads();
    float r = (threadIdx.x < (blockDim.x >> 5)) ? sh[threadIdx.x] : 0.0f;
    if (w == 0) {
        #pragma unroll
        for (int o = 16; o; o >>= 1) r += __shfl_xor_sync(0xFFFFFFFFu, r, o);
        if (lane == 0) sh[0] = r;
    }
    __syncthreads();
    float out = sh[0];
    __syncthreads();
    return out;
}

// ---------------------------------------------------------------------------
// fp32 -> fp16 convert (vectorized)
// ---------------------------------------------------------------------------
__global__ void tohalf_kernel(const float* __restrict__ s,
                              __half* __restrict__ d, size_t n4)
{
    size_t i = (size_t)blockIdx.x * blockDim.x + threadIdx.x;
    if (i >= n4) return;
    float4 v = reinterpret_cast<const float4*>(s)[i];
    __half2 h0 = __floats2half2_rn(v.x, v.y);
    __half2 h1 = __floats2half2_rn(v.z, v.w);
    uint2 o;
    o.x = *reinterpret_cast<uint32_t*>(&h0);
    o.y = *reinterpret_cast<uint32_t*>(&h1);
    reinterpret_cast<uint2*>(d)[i] = o;
}

// ---------------------------------------------------------------------------
// Single-pass fp16 HMMA GEMM: C[M,N] = act(A*B^T + bias) (+ residual)
// MODE bits: 1=gelu, 2=+Xres, 4=split-A, 8=dual-output (blocks with
//   blockIdx.x >= NXtiles use the second matrix set; second output gelued).
// BM=BN=128, BK=64, 3-stage cp.async, 256 threads, 2 CTAs/SM.
// ---------------------------------------------------------------------------
template<int MODE>
__global__ void __launch_bounds__(256, 2)
mma_gemm(const __half* __restrict__ A, const __half* __restrict__ A2,
         const __half* __restrict__ Bm,
         const float* __restrict__ bias, const float* __restrict__ Xres,
         float* __restrict__ C, int N, int K, int Ksplit, int strideA,
         const __half* __restrict__ B2,
         const float* __restrict__ bias2, float* __restrict__ C2,
         int N2, int NXtiles)
{
    constexpr int BM = 128, BK = 64, STAGES = 3;
    constexpr int TILE_B  = BM * BK * 2;      // 16384 bytes per matrix tile
    constexpr int STAGE_B = 2 * TILE_B;       // A + B

    extern __shared__ __align__(16) char smem[];
    const uint32_t sbase = smem_to_u32(smem);

    const int tid  = threadIdx.x;
    const int wid  = tid >> 5, lane = tid & 31;
    const int m0 = blockIdx.y * BM;

    int bx = blockIdx.x;
    bool second = false;
    if constexpr (MODE & 8) {
        if (bx >= NXtiles) { second = true; bx -= NXtiles; }
    }
    const __half* pB = second ? B2 : Bm;
    const float* pbias = second ? bias2 : bias;
    float* pC = second ? C2 : C;
    const int NN = second ? N2 : N;
    const int n0 = bx * BM;
    const bool do_gelu = (MODE & 1) || second;

    const int wm = (wid >> 2) * 64;
    const int wn = (wid & 3) * 32;

    float acc[4][4][4];
    #pragma unroll
    for (int i = 0; i < 4; i++)
        #pragma unroll
        for (int j = 0; j < 4; j++)
            #pragma unroll
            for (int k = 0; k < 4; k++) acc[i][j][k] = 0.0f;

    const int nk = K / BK;

    auto load_stage = [&](int s, int t) {
        const int k0 = t * BK;
        const __half* pA = A;
        int ka = k0;
        if constexpr (MODE & 4) {
            if (k0 >= Ksplit) { pA = A2; ka = k0 - Ksplit; }
        }
        const uint32_t sb = sbase + s * STAGE_B;
        // each matrix tile: 128 rows x 128 bytes = 1024 x 16B chunks
        #pragma unroll
        for (int i = 0; i < 4; i++) {
            int idx = tid + i * 256;
            int row = idx >> 3, g = idx & 7;
            int gs  = g ^ (row & 7);
            uint32_t so = row * 128 + gs * 16;
            size_t ga = (size_t)(m0 + row) * strideA + ka + g * 8;
            size_t gb = (size_t)(n0 + row) * K + k0 + g * 8;
            cpasync16(sb + so, pA + ga);
            cpasync16(sb + TILE_B + so, pB + gb);
        }
    };

    auto compute_stage = [&](int s) {
        const uint32_t sb = sbase + s * STAGE_B;
        #pragma unroll
        for (int ks = 0; ks < 4; ks++) {
            uint32_t afr[4][4], bfr[2][4];
            #pragma unroll
            for (int mf = 0; mf < 4; mf++) {
                int row = wm + mf * 16 + (lane & 15);
                int g   = ks * 2 + (lane >> 4);
                ldsm4(afr[mf], sb + row * 128 + ((g ^ (row & 7)) * 16));
            }
            #pragma unroll
            for (int nf2 = 0; nf2 < 2; nf2++) {
                int nrow = wn + nf2 * 16 + ((lane >> 4) & 1) * 8 + (lane & 7);
                int g    = ks * 2 + ((lane >> 3) & 1);
                ldsm4(bfr[nf2], sb + TILE_B + nrow * 128 + ((g ^ (nrow & 7)) * 16));
            }
            #pragma unroll
            for (int mf = 0; mf < 4; mf++)
                #pragma unroll
                for (int nf = 0; nf < 4; nf++)
                    mma_f16(acc[mf][nf], afr[mf], &bfr[nf >> 1][(nf & 1) * 2]);
        }
    };

    load_stage(0, 0); CP_COMMIT();
    load_stage(1, 1); CP_COMMIT();

    for (int t = 0; t < nk; t++) {
        CP_WAIT(STAGES - 2);
        __syncthreads();
        if (t + STAGES - 1 < nk) load_stage((t + STAGES - 1) % STAGES, t + STAGES - 1);
        CP_COMMIT();
        compute_stage(t % STAGES);
    }

    #pragma unroll
    for (int mf = 0; mf < 4; mf++)
        #pragma unroll
        for (int nf = 0; nf < 4; nf++)
            #pragma unroll
            for (int half = 0; half < 2; half++) {
                int row = m0 + wm + mf * 16 + (lane >> 2) + half * 8;
                int col = n0 + wn + nf * 8 + (lane & 3) * 2;
                float v0 = acc[mf][nf][half * 2 + 0] + pbias[col];
                float v1 = acc[mf][nf][half * 2 + 1] + pbias[col + 1];
                if (do_gelu) { v0 = gelu_exact(v0); v1 = gelu_exact(v1); }
                if constexpr (MODE & 2) {
                    float2 xr = *reinterpret_cast<const float2*>(
                        &Xres[(size_t)row * NN + col]);
                    v0 += xr.x; v1 += xr.y;
                }
                float2 o; o.x = v0; o.y = v1;
                *reinterpret_cast<float2*>(&pC[(size_t)row * NN + col]) = o;
            }
}

// ---------------------------------------------------------------------------
// Fused: row-norms of h + sim GEMM (h @ pn^T) + salience + softmax -> attn
// BM=128, BN=64 (= S), BK=16, 256 threads, fp32 SIMT.
// ---------------------------------------------------------------------------
__global__ void __launch_bounds__(256)
sim_attn_kernel(const float* __restrict__ A, const float* __restrict__ Bm,
                const float* __restrict__ tw, float* __restrict__ attn)
{
    constexpr int BM = 128, BN = 64, BK = 16, TM = 8, TN = 4, PAD = 4;
    constexpr int KV = BK / 4;
    constexpr int AS_B = 2 * BK * (BM + PAD) * 4;
    constexpr int SSQ_OFF = 33280;

    extern __shared__ __align__(16) char dsm[];
    float (*As)[BK][BM + PAD] = reinterpret_cast<float (*)[BK][BM + PAD]>(dsm);
    float (*Bs)[BK][BN + PAD] = reinterpret_cast<float (*)[BK][BN + PAD]>(dsm + AS_B);
    float* sal = reinterpret_cast<float*>(dsm);
    float* ssq_sm = reinterpret_cast<float*>(dsm + SSQ_OFF);

    const int tid = threadIdx.x;
    const int m0 = blockIdx.y * BM;
    const int tr = tid / 16;
    const int tc = tid % 16;

    const int K = D_DIM;
    float4 aReg[2]; float4 bReg;
    float acc[TM][TN];
    float ssq[2] = {0.f, 0.f};
    #pragma unroll
    for (int i = 0; i < TM; i++)
        #pragma unroll
        for (int j = 0; j < TN; j++) acc[i][j] = 0.0f;

    auto fetch = [&](int kt) {
        #pragma unroll
        for (int i = 0; i < 2; i++) {
            int idx = tid + i * 256;
            int row = idx / KV, kc = (idx % KV) * 4;
            aReg[i] = *reinterpret_cast<const float4*>(A + (size_t)(m0+row)*K + kt + kc);
            ssq[i] += aReg[i].x*aReg[i].x + aReg[i].y*aReg[i].y
                    + aReg[i].z*aReg[i].z + aReg[i].w*aReg[i].w;
        }
        {
            int row = tid / KV, kc = (tid % KV) * 4;
            bReg = *reinterpret_cast<const float4*>(Bm + (size_t)row*K + kt + kc);
        }
    };
    auto stash = [&](int buf) {
        #pragma unroll
        for (int i = 0; i < 2; i++) {
            int idx = tid + i * 256;
            int row = idx / KV, kc = (idx % KV) * 4;
            As[buf][kc+0][row] = aReg[i].x; As[buf][kc+1][row] = aReg[i].y;
            As[buf][kc+2][row] = aReg[i].z; As[buf][kc+3][row] = aReg[i].w;
        }
        {
            int row = tid / KV, kc = (tid % KV) * 4;
            Bs[buf][kc+0][row] = bReg.x; Bs[buf][kc+1][row] = bReg.y;
            Bs[buf][kc+2][row] = bReg.z; Bs[buf][kc+3][row] = bReg.w;
        }
    };

    fetch(0); stash(0);
    __syncthreads();

    const int nk = K / BK;
    for (int t = 0; t < nk; t++) {
        const int cur = t & 1;
        if (t + 1 < nk) fetch((t + 1) * BK);
        #pragma unroll
        for (int k = 0; k < BK; k++) {
            float a[TM], b[TN];
            #pragma unroll
            for (int i = 0; i < TM; i += 4) {
                float4 v = *reinterpret_cast<const float4*>(&As[cur][k][tr*TM + i]);
                a[i]=v.x; a[i+1]=v.y; a[i+2]=v.z; a[i+3]=v.w;
            }
            #pragma unroll
            for (int j = 0; j < TN; j += 4) {
                float4 v = *reinterpret_cast<const float4*>(&Bs[cur][k][tc*TN + j]);
                b[j]=v.x; b[j+1]=v.y; b[j+2]=v.z; b[j+3]=v.w;
            }
            #pragma unroll
            for (int i = 0; i < TM; i++)
                #pragma unroll
                for (int j = 0; j < TN; j++)
                    acc[i][j] = fmaf(a[i], b[j], acc[i][j]);
        }
        if (t + 1 < nk) stash(cur ^ 1);
        __syncthreads();
    }

    #pragma unroll
    for (int i = 0; i < 2; i++) {
        ssq[i] += __shfl_xor_sync(0xFFFFFFFFu, ssq[i], 1);
        ssq[i] += __shfl_xor_sync(0xFFFFFFFFu, ssq[i], 2);
    }
    if ((tid & 3) == 0) {
        ssq_sm[tid / 4]      = ssq[0];
        ssq_sm[64 + tid / 4] = ssq[1];
    }
    __syncthreads();

    #pragma unroll
    for (int i = 0; i < TM; i++) {
        int row = tr * TM + i;
        float invn = 1.0f / fmaxf(sqrtf(ssq_sm[row]), 1e-12f);
        float twv = tw[(size_t)(m0 + row) * 4 + (tc >> 2)];
        #pragma unroll
        for (int j = 0; j < TN; j++) {
            int col = tc * TN + j;
            float v = g_wsimc[col] * twv * (acc[i][j] * invn) + g_base[col];
            sal[row * 65 + col] = fminf(fmaxf(v, 0.0f), 1.0f);
        }
    }
    __syncthreads();

    {
        int row = tid >> 1, half = tid & 1;
        const float* srow = &sal[row * 65 + half * 32];
        float m = -1e30f;
        #pragma unroll
        for (int c = 0; c < 32; c++) m = fmaxf(m, srow[c]);
        m = fmaxf(m, __shfl_xor_sync(0xFFFFFFFFu, m, 1));
        const float invT = 1.0f / 0.07f;
        float e[32], s = 0.0f;
        #pragma unroll
        for (int c = 0; c < 32; c++) { e[c] = expf((srow[c] - m) * invT); s += e[c]; }
        s += __shfl_xor_sync(0xFFFFFFFFu, s, 1);
        float inv = 1.0f / s;
        float* dst = &attn[(size_t)(m0 + row) * S_PROTO + half * 32];
        #pragma unroll
        for (int c = 0; c < 32; c += 4) {
            float4 o; o.x = e[c]*inv; o.y = e[c+1]*inv; o.z = e[c+2]*inv; o.w = e[c+3]*inv;
            *reinterpret_cast<float4*>(dst + c) = o;
        }
    }
}

// ---------------------------------------------------------------------------
// Prototype prep
// ---------------------------------------------------------------------------
__global__ void proto_prep(const float* __restrict__ protos,
                           const float* __restrict__ conf,
                           const float* __restrict__ age,
                           const float* __restrict__ ev)
{
    const int s = blockIdx.x;
    float ss = 0.0f;
    for (int k = threadIdx.x; k < D_DIM; k += 256) {
        float v = protos[(size_t)s * D_DIM + k];
        ss += v * v;
    }
    float tot = block_reduce_sum(ss);
    float scale = 1.0f / fmaxf(sqrtf(tot), 1e-12f);
    for (int k = threadIdx.x; k < D_DIM; k += 256)
        g_pn[(size_t)s * D_DIM + k] = protos[(size_t)s * D_DIM + k] * scale;

    if (threadIdx.x == 0) {
        float evmax = 0.0f;
        for (int i = 0; i < S_PROTO; i++) evmax = fmaxf(evmax, ev[i]);
        float freq = logf(ev[s] + 1.0f) / (logf(evmax + 2.0f) + 1e-8f);
        float rec  = expf(-age[s] * (1.0f / 200.0f));
        g_base[s]  = 0.2f * rec + 0.15f * freq + 0.1f * conf[s] + 0.1f * 0.9f;
        g_wsimc[s] = 0.45f * conf[s];
    }
}

// ---------------------------------------------------------------------------
// Type weights softmax (4 logits). 1 warp per row.
// ---------------------------------------------------------------------------
__global__ void type_weights_kernel(const float* __restrict__ r,
                                    const float* __restrict__ Wr2,
                                    const float* __restrict__ br2,
                                    float* __restrict__ tw)
{
    const int warp = threadIdx.x >> 5, lane = threadIdx.x & 31;
    const int b = blockIdx.x * 8 + warp;
    const float4* rp = reinterpret_cast<const float4*>(r + (size_t)b * D_HALF);
    float acc[4] = {0.f, 0.f, 0.f, 0.f};
    for (int i = lane; i < D_HALF / 4; i += 32) {
        float4 rv = rp[i];
        #pragma unroll
        for (int t = 0; t < 4; t++) {
            float4 wv = reinterpret_cast<const float4*>(Wr2 + (size_t)t * D_HALF)[i];
            acc[t] += rv.x*wv.x + rv.y*wv.y + rv.z*wv.z + rv.w*wv.w;
        }
    }
    #pragma unroll
    for (int t = 0; t < 4; t++)
        #pragma unroll
        for (int o = 16; o; o >>= 1)
            acc[t] += __shfl_xor_sync(0xFFFFFFFFu, acc[t], o);
    if (lane == 0) {
        float z[4], m = -1e30f;
        #pragma unroll
        for (int t = 0; t < 4; t++) { z[t] = acc[t] + br2[t]; m = fmaxf(m, z[t]); }
        float s = 0.0f;
        #pragma unroll
        for (int t = 0; t < 4; t++) { z[t] = expf(z[t] - m); s += z[t]; }
        float inv = 1.0f / s;
        #pragma unroll
        for (int t = 0; t < 4; t++) tw[(size_t)b * 4 + t] = z[t] * inv;
    }
}

// ---------------------------------------------------------------------------
// retrieved = attn @ prototypes, written as fp16.
// ---------------------------------------------------------------------------
__global__ void retrieve_kernel(const float* __restrict__ attn,
                                const float* __restrict__ protos,
                                __half* __restrict__ out_h)
{
    __shared__ float sA[16][S_PROTO];
    const int tid = threadIdx.x;
    const int r0 = blockIdx.y * 16;
    for (int i = tid; i < 16 * S_PROTO; i += 256)
        sA[i / S_PROTO][i % S_PROTO] =
            attn[(size_t)(r0 + i / S_PROTO) * S_PROTO + (i % S_PROTO)];
    __syncthreads();

    const int n = blockIdx.x * 256 + tid;
    float acc[16];
    #pragma unroll
    for (int r = 0; r < 16; r++) acc[r] = 0.0f;
    for (int s = 0; s < S_PROTO; s++) {
        float p = protos[(size_t)s * D_DIM + n];
        #pragma unroll
        for (int r = 0; r < 16; r++) acc[r] = fmaf(sA[r][s], p, acc[r]);
    }
    #pragma unroll
    for (int r = 0; r < 16; r++)
        out_h[(size_t)(r0 + r) * D_DIM + n] = __float2half_rn(acc[r]);
}

// ---------------------------------------------------------------------------
// In-place LayerNorm over D
// ---------------------------------------------------------------------------
__global__ void layernorm_inplace(float* __restrict__ y,
                                  const float* __restrict__ w,
                                  const float* __restrict__ bb)
{
    const size_t base = (size_t)blockIdx.x * D_DIM;
    float4* yp = reinterpret_cast<float4*>(y + base);
    float4 v[2];
    float sum = 0.0f;
    #pragma unroll
    for (int i = 0; i < 2; i++) {
        v[i] = yp[threadIdx.x + 256 * i];
        sum += v[i].x + v[i].y + v[i].z + v[i].w;
    }
    float mu = block_reduce_sum(sum) * (1.0f / D_DIM);
    float sq = 0.0f;
    #pragma unroll
    for (int i = 0; i < 2; i++) {
        float dx = v[i].x - mu, dy = v[i].y - mu, dz = v[i].z - mu, dw = v[i].w - mu;
        sq += dx*dx + dy*dy + dz*dz + dw*dw;
    }
    float var = block_reduce_sum(sq) * (1.0f / D_DIM);
    float rstd = rsqrtf(var + 1e-5f);
    #pragma unroll
    for (int i = 0; i < 2; i++) {
        int col = (threadIdx.x + 256 * i) * 4;
        float4 wv = *reinterpret_cast<const float4*>(&w[col]);
        float4 bv = *reinterpret_cast<const float4*>(&bb[col]);
        float4 o;
        o.x = wv.x * (v[i].x - mu) * rstd + bv.x;
        o.y = wv.y * (v[i].y - mu) * rstd + bv.y;
        o.z = wv.z * (v[i].z - mu) * rstd + bv.z;
        o.w = wv.w * (v[i].w - mu) * rstd + bv.w;
        yp[threadIdx.x + 256 * i] = o;
    }
}

// ---------------------------------------------------------------------------
// Launch
// ---------------------------------------------------------------------------
extern "C" void kernel_launch(void* const* d_in, const int* in_sizes, int n_in,
                              void* d_out, int out_size)
{
    const float* x      = (const float*)d_in[0];
    const float* protos = (const float*)d_in[1];
    const float* conf   = (const float*)d_in[2];
    const float* age    = (const float*)d_in[3];
    const float* ev     = (const float*)d_in[4];
    const float* W_in   = (const float*)d_in[5];
    const float* b_in   = (const float*)d_in[6];
    const float* Wr1    = (const float*)d_in[7];
    const float* br1    = (const float*)d_in[8];
    const float* Wr2    = (const float*)d_in[9];
    const float* br2    = (const float*)d_in[10];
    const float* W_out  = (const float*)d_in[11];
    const float* b_out  = (const float*)d_in[12];
    const float* ln_w   = (const float*)d_in[13];
    const float* ln_b   = (const float*)d_in[14];
    float* out = (float*)d_out;

    __half *xh, *winh, *wr1h, *wouth, *reth;
    float *h, *r, *tw, *attn, *pn;
    cudaGetSymbolAddress((void**)&xh,    g_x_h);
    cudaGetSymbolAddress((void**)&winh,  g_Win_h);
    cudaGetSymbolAddress((void**)&wr1h,  g_Wr1_h);
    cudaGetSymbolAddress((void**)&wouth, g_Wout_h);
    cudaGetSymbolAddress((void**)&reth,  g_retr_h);
    cudaGetSymbolAddress((void**)&h,    g_h);
    cudaGetSymbolAddress((void**)&r,    g_r);
    cudaGetSymbolAddress((void**)&tw,   g_tw);
    cudaGetSymbolAddress((void**)&attn, g_attn);
    cudaGetSymbolAddress((void**)&pn,   g_pn);

    constexpr int SMEM_SZ = 3 * 2 * 128 * 64 * 2;   // 98304 bytes
    cudaFuncSetAttribute(mma_gemm<8>, cudaFuncAttributeMaxDynamicSharedMemorySize, SMEM_SZ);
    cudaFuncSetAttribute(mma_gemm<7>, cudaFuncAttributeMaxDynamicSharedMemorySize, SMEM_SZ);

    const int B = B_ROWS;

    // fp16 conversions
    {
        size_t n4;
        n4 = (size_t)B * D_DIM / 4;
        tohalf_kernel<<<(unsigned)((n4 + 255) / 256), 256>>>(x, xh, n4);
        n4 = (size_t)D_DIM * D_DIM / 4;
        tohalf_kernel<<<(unsigned)((n4 + 255) / 256), 256>>>(W_in, winh, n4);
        n4 = (size_t)D_HALF * D_DIM / 4;
        tohalf_kernel<<<(unsigned)((n4 + 255) / 256), 256>>>(Wr1, wr1h, n4);
        n4 = (size_t)D_DIM * 2 * D_DIM / 4;
        tohalf_kernel<<<(unsigned)((n4 + 255) / 256), 256>>>(W_out, wouth, n4);
    }

    proto_prep<<<S_PROTO, 256>>>(protos, conf, age, ev);

    // G1+G2 fused: h = x@W_in^T + b_in ; r = gelu(x@Wr1^T + br1)
    mma_gemm<8><<<dim3(D_DIM / 128 + D_HALF / 128, B / 128), 256, SMEM_SZ>>>(
        xh, nullptr, winh, b_in, nullptr, h,
        D_DIM, D_DIM, 0, D_DIM,
        wr1h, br1, r, D_HALF, D_DIM / 128);

    type_weights_kernel<<<B / 8, 256>>>(r, Wr2, br2, tw);

    // fused rownorm + sim + salience + softmax -> attn
    sim_attn_kernel<<<dim3(1, B / 128), 256, 33792>>>(h, pn, tw, attn);

    // retrieved (fp16)
    retrieve_kernel<<<dim3(D_DIM / 256, B / 16), 256>>>(attn, protos, reth);

    // G3: out = gelu([x, retrieved] @ W_out^T + b_out) + x
    mma_gemm<7><<<dim3(D_DIM / 128, B / 128), 256, SMEM_SZ>>>(
        xh, reth, wouth, b_out, x, out,
        D_DIM, 2 * D_DIM, D_DIM, D_DIM,
        nullptr, nullptr, nullptr, 0, 0x7FFFFFFF);

    layernorm_inplace<<<B, 256>>>(out, ln_w, ln_b);
}